// round 13
// baseline (speedup 1.0000x reference)
#include <cuda_runtime.h>
#include <cuda_bf16.h>
#include <mma.h>
#include <cstddef>

using namespace nvcuda;

// ---------------- scratch (static __device__, no allocs) ----------------
__device__ float g_feas[3 * 512 * 1024];
__device__ float g_bsum[3 * 512];
__device__ float g_fz[32];
__device__ float g_outres[512 * 1024];
__device__ float g_fgsT[256 * 512];       // fg_small, pixel-major [pos][c]
__device__ float g_S[8 * 256 * 256];      // split-K partials of R = F F^T
__device__ float g_R[256 * 256];          // reduced R
__device__ float g_attnT[256 * 256];      // attn transposed: [q][p]
__device__ float g_T[256 * 8192];         // T'[q][row]; reused for gaussian stage-1
__device__ float g_out32T[1024 * 512];    // post-RAL out_32, pixel-major
__device__ float g_z[1024 * 1024];        // concat(gus_out, out_csa)
__device__ float g_d1[4 * 512 * 1024];    // split-K partials of down/fuse
__device__ float g_z2[1024 * 1024];       // concat(leaky(norm(down)), out_res)

// ---------------- helpers ----------------
__device__ __forceinline__ void blockReduce2(float& s, float& s2, float* sm) {
    __syncthreads();
    int tid = threadIdx.x;
    #pragma unroll
    for (int o = 16; o > 0; o >>= 1) {
        s  += __shfl_down_sync(0xFFFFFFFFu, s, o);
        s2 += __shfl_down_sync(0xFFFFFFFFu, s2, o);
    }
    int w = tid >> 5, l = tid & 31;
    int nw = blockDim.x >> 5;
    if (l == 0) { sm[w] = s; sm[32 + w] = s2; }
    __syncthreads();
    if (tid < 32) {
        s  = (tid < nw) ? sm[tid] : 0.f;
        s2 = (tid < nw) ? sm[32 + tid] : 0.f;
        #pragma unroll
        for (int o = 16; o > 0; o >>= 1) {
            s  += __shfl_down_sync(0xFFFFFFFFu, s, o);
            s2 += __shfl_down_sync(0xFFFFFFFFu, s2, o);
        }
        if (tid == 0) { sm[0] = s; sm[32] = s2; }
    }
    __syncthreads();
    s = sm[0]; s2 = sm[32];
}

__device__ __forceinline__ void mma_bf16(float c[4], const unsigned a[4], const unsigned b[2]) {
    asm volatile(
        "mma.sync.aligned.m16n8k16.row.col.f32.bf16.bf16.f32 "
        "{%0,%1,%2,%3}, {%4,%5,%6,%7}, {%8,%9}, {%0,%1,%2,%3};\n"
        : "+f"(c[0]), "+f"(c[1]), "+f"(c[2]), "+f"(c[3])
        : "r"(a[0]), "r"(a[1]), "r"(a[2]), "r"(a[3]), "r"(b[0]), "r"(b[1]));
}

// ------- 1) SK grouped conv via tensor cores (no im2col) + fused IN + relu -------
// X staged pixel-major [padded_pix][ic] (bf16 hi/lo) -> B operand of mma is a
// col-major (ld=16) view at a tap-shifted base. Weights [tap][oc][ic] -> A row-major.
// Conv bias cancels under instance norm and is omitted.
template <int KS>
__device__ __forceinline__ void sk_mma_impl(
    const float* __restrict__ x, const float* __restrict__ w,
    int branch, char* sm) {
    constexpr int PAD = KS / 2;
    constexpr int W = 32 + 2 * PAD;
    constexpr int NPIX = W * W;
    constexpr int NT = KS * KS;
    __nv_bfloat16* Xh = (__nv_bfloat16*)sm;            // [NPIX][16]
    __nv_bfloat16* Xl = Xh + NPIX * 16;
    __nv_bfloat16* Wh = Xl + NPIX * 16;                // [NT][16 oc][16 ic]
    __nv_bfloat16* Wl = Wh + NT * 256;
    float* outb = (float*)sm;                          // [16 oc][1024], aliases X after sync

    int gidx = blockIdx.x;
    int tid = threadIdx.x;

    // zero X planes (borders must be 0)
    for (int i = tid; i < NPIX * 8; i += 512) {
        ((unsigned*)Xh)[i] = 0u;
        ((unsigned*)Xl)[i] = 0u;
    }
    __syncthreads();
    // stage X group: [pix][ic], hi/lo split
    const float* xg = x + (size_t)gidx * 16 * 1024;
    for (int i = tid; i < 16 * 1024; i += 512) {
        int ic = i >> 10, pix = i & 1023;
        int py = pix >> 5, px = pix & 31;
        float v = xg[i];
        __nv_bfloat16 h = __float2bfloat16(v);
        __nv_bfloat16 l = __float2bfloat16(v - __bfloat162float(h));
        int sp = ((py + PAD) * W + px + PAD) * 16 + ic;
        Xh[sp] = h; Xl[sp] = l;
    }
    // stage weights: [tap][oc][ic], hi/lo
    const float* wg = w + (size_t)gidx * 16 * 16 * NT;
    for (int i = tid; i < 16 * 16 * NT; i += 512) {
        int oc = i / (16 * NT);
        int rem = i - oc * 16 * NT;
        int ic = rem / NT;
        int tap = rem - ic * NT;
        float v = wg[i];
        __nv_bfloat16 h = __float2bfloat16(v);
        __nv_bfloat16 l = __float2bfloat16(v - __bfloat162float(h));
        int sp = tap * 256 + oc * 16 + ic;
        Wh[sp] = h; Wl[sp] = l;
    }
    __syncthreads();

    int warp = tid >> 5, lane = tid & 31;
    int gq = lane >> 2, tq = lane & 3;
    int row0 = warp * 2;                   // each warp owns 2 output rows (64 px)
    float acc[8][4] = {};

    #pragma unroll 1
    for (int tap = 0; tap < NT; tap++) {
        int ky = tap / KS, kx = tap - ky * KS;
        const __nv_bfloat16* wth = &Wh[tap * 256];
        const __nv_bfloat16* wtl = &Wl[tap * 256];
        unsigned ah[4], al[4];
        ah[0] = *(const unsigned*)&wth[gq * 16 + tq * 2];
        ah[1] = *(const unsigned*)&wth[(gq + 8) * 16 + tq * 2];
        ah[2] = *(const unsigned*)&wth[gq * 16 + tq * 2 + 8];
        ah[3] = *(const unsigned*)&wth[(gq + 8) * 16 + tq * 2 + 8];
        al[0] = *(const unsigned*)&wtl[gq * 16 + tq * 2];
        al[1] = *(const unsigned*)&wtl[(gq + 8) * 16 + tq * 2];
        al[2] = *(const unsigned*)&wtl[gq * 16 + tq * 2 + 8];
        al[3] = *(const unsigned*)&wtl[(gq + 8) * 16 + tq * 2 + 8];
        #pragma unroll
        for (int nt = 0; nt < 8; nt++) {
            int r = row0 + (nt >> 2);
            int c = nt & 3;
            int pixg = (r + ky) * W + c * 8 + kx + gq;
            const __nv_bfloat16* bhp = &Xh[pixg * 16 + tq * 2];
            const __nv_bfloat16* blp = &Xl[pixg * 16 + tq * 2];
            unsigned bh[2], bl[2];
            bh[0] = *(const unsigned*)bhp;
            bh[1] = *(const unsigned*)(bhp + 8);
            bl[0] = *(const unsigned*)blp;
            bl[1] = *(const unsigned*)(blp + 8);
            mma_bf16(acc[nt], ah, bh);
            mma_bf16(acc[nt], ah, bl);
            mma_bf16(acc[nt], al, bh);
        }
    }
    __syncthreads();   // all X reads done before aliasing with outb

    #pragma unroll
    for (int nt = 0; nt < 8; nt++) {
        int r = row0 + (nt >> 2);
        int c = nt & 3;
        int pix = r * 32 + c * 8 + tq * 2;
        outb[gq * 1024 + pix]           = acc[nt][0];
        outb[gq * 1024 + pix + 1]       = acc[nt][1];
        outb[(gq + 8) * 1024 + pix]     = acc[nt][2];
        outb[(gq + 8) * 1024 + pix + 1] = acc[nt][3];
    }
    __syncthreads();

    // instance norm + relu + bsum: one warp per oc
    int oc = warp;
    float s = 0.f, s2 = 0.f;
    for (int j = 0; j < 32; j++) {
        float v = outb[oc * 1024 + j * 32 + lane];
        s += v; s2 += v * v;
    }
    #pragma unroll
    for (int o = 16; o > 0; o >>= 1) {
        s  += __shfl_down_sync(0xFFFFFFFFu, s, o);
        s2 += __shfl_down_sync(0xFFFFFFFFu, s2, o);
    }
    s = __shfl_sync(0xFFFFFFFFu, s, 0);
    s2 = __shfl_sync(0xFFFFFFFFu, s2, 0);
    float mu = s * (1.f / 1024.f);
    float var = s2 * (1.f / 1024.f) - mu * mu;
    float inv = rsqrtf(var + 1e-5f);
    float* fo = &g_feas[(size_t)branch * 512 * 1024 + (size_t)(gidx * 16 + oc) * 1024];
    float rs = 0.f;
    for (int j = 0; j < 32; j++) {
        float v = outb[oc * 1024 + j * 32 + lane];
        float r = fmaxf((v - mu) * inv, 0.f);
        fo[j * 32 + lane] = r;
        rs += r;
    }
    #pragma unroll
    for (int o = 16; o > 0; o >>= 1) rs += __shfl_down_sync(0xFFFFFFFFu, rs, o);
    if (lane == 0) g_bsum[branch * 512 + gidx * 16 + oc] = rs;
}

__global__ __launch_bounds__(512) void sk_mma_all(
    const float* __restrict__ x,
    const float* __restrict__ w3,
    const float* __restrict__ w5,
    const float* __restrict__ w7) {
    extern __shared__ char sm[];
    int br = blockIdx.y;
    if (br == 0)      sk_mma_impl<3>(x, w3, 0, sm);
    else if (br == 1) sk_mma_impl<5>(x, w5, 1, sm);
    else              sk_mma_impl<7>(x, w7, 2, sm);
}

static const int SMEM_SK = (38 * 38 * 16 * 2) * 2 + (49 * 256 * 2) * 2;  // 142,592 B

// ---------------- 2) FC1 ----------------
__global__ __launch_bounds__(256) void fz_kernel(
    const float* __restrict__ w_fc, const float* __restrict__ b_fc) {
    __shared__ float s_red[64];
    int j = blockIdx.x, tid = threadIdx.x;
    float s = 0.f;
    for (int c = tid; c < 512; c += 256) {
        float fs = (g_bsum[c] + g_bsum[512 + c] + g_bsum[1024 + c]) * (1.f / 1024.f);
        s += fs * w_fc[j * 512 + c];
    }
    float dummy = 0.f;
    blockReduce2(s, dummy, s_red);
    if (tid == 0) g_fz[j] = s + b_fc[j];
}

// ------- 3) per-channel branch attention + combine -> out_res; avg pool -> fgsT ------
__global__ __launch_bounds__(256) void combine_kernel(
    const float* __restrict__ w0, const float* __restrict__ b0,
    const float* __restrict__ w1, const float* __restrict__ b1,
    const float* __restrict__ w2, const float* __restrict__ b2) {
    int c = blockIdx.x, tid = threadIdx.x;
    __shared__ float s_fz[32];
    __shared__ float s_a[3];
    __shared__ float s_o[1024];
    if (tid < 32) s_fz[tid] = g_fz[tid];
    __syncthreads();
    int w = tid >> 5, l = tid & 31;
    if (w < 3) {
        const float* wt = (w == 0) ? w0 : (w == 1) ? w1 : w2;
        const float* bt = (w == 0) ? b0 : (w == 1) ? b1 : b2;
        float v = s_fz[l] * wt[c * 32 + l];
        #pragma unroll
        for (int o = 16; o > 0; o >>= 1) v += __shfl_down_sync(0xFFFFFFFFu, v, o);
        if (l == 0) s_a[w] = v + bt[c];
    }
    __syncthreads();
    float A0 = s_a[0], A1 = s_a[1], A2 = s_a[2];
    float mx = fmaxf(A0, fmaxf(A1, A2));
    float e0 = __expf(A0 - mx), e1 = __expf(A1 - mx), e2 = __expf(A2 - mx);
    float inv = 1.f / (e0 + e1 + e2);
    float a0 = e0 * inv, a1 = e1 * inv, a2 = e2 * inv;

    for (int i = tid; i < 1024; i += 256) {
        float v = a0 * g_feas[(size_t)c * 1024 + i]
                + a1 * g_feas[512 * 1024 + (size_t)c * 1024 + i]
                + a2 * g_feas[2 * 512 * 1024 + (size_t)c * 1024 + i];
        g_outres[c * 1024 + i] = v;
        s_o[i] = v;
    }
    __syncthreads();
    int py = tid >> 4, px = tid & 15;
    float p = 0.25f * (s_o[(2 * py) * 32 + 2 * px] + s_o[(2 * py) * 32 + 2 * px + 1] +
                       s_o[(2 * py + 1) * 32 + 2 * px] + s_o[(2 * py + 1) * 32 + 2 * px + 1]);
    g_fgsT[(size_t)tid * 512 + c] = p;
}

// ---- fp32 64x64-tile NT SGEMM for R = F F^T (k-tile 16, split-K) ----
__global__ __launch_bounds__(256) void gemm64_nt(
    const float* __restrict__ A, float* __restrict__ C,
    int M, int K, int ksplit) {
    __shared__ float As[16][68];
    __shared__ float Bs[16][68];
    int tid = threadIdx.x;
    int bm = blockIdx.y * 64, bn = blockIdx.x * 64;
    int kchunk = K / ksplit, k0 = blockIdx.z * kchunk, kend = k0 + kchunk;
    C += (size_t)blockIdx.z * M * M;
    int lr = tid >> 2, lc = (tid & 3) * 4;
    int tx = tid & 15, ty = tid >> 4;

    float4 pa, pb;
    auto loadAB = [&](int kk) {
        pa = *(const float4*)(A + (size_t)(bm + lr) * K + kk + lc);
        pb = *(const float4*)(A + (size_t)(bn + lr) * K + kk + lc);
    };
    auto storeTiles = [&]() {
        As[lc][lr] = pa.x; As[lc + 1][lr] = pa.y; As[lc + 2][lr] = pa.z; As[lc + 3][lr] = pa.w;
        Bs[lc][lr] = pb.x; Bs[lc + 1][lr] = pb.y; Bs[lc + 2][lr] = pb.z; Bs[lc + 3][lr] = pb.w;
    };

    float acc[4][4] = {};
    loadAB(k0);
    for (int kk = k0; kk < kend; kk += 16) {
        storeTiles();
        __syncthreads();
        if (kk + 16 < kend) loadAB(kk + 16);
        #pragma unroll
        for (int k = 0; k < 16; k++) {
            float4 a = *(const float4*)&As[k][ty * 4];
            float4 b = *(const float4*)&Bs[k][tx * 4];
            float ar[4] = {a.x, a.y, a.z, a.w};
            float br[4] = {b.x, b.y, b.z, b.w};
            #pragma unroll
            for (int i = 0; i < 4; i++)
                #pragma unroll
                for (int j = 0; j < 4; j++) acc[i][j] += ar[i] * br[j];
        }
        __syncthreads();
    }
    #pragma unroll
    for (int i = 0; i < 4; i++)
        *(float4*)(C + (size_t)(bm + ty * 4 + i) * M + bn + tx * 4) =
            make_float4(acc[i][0], acc[i][1], acc[i][2], acc[i][3]);
}

// ---- bf16x2-split WMMA 128x128-tile GEMM (3-mma Ootomo) ----
template <bool BT, bool GATHER>
__global__ __launch_bounds__(256) void gemm128_bf16(
    const float* __restrict__ A, const float* __restrict__ B, float* __restrict__ C,
    int M, int N, int K, int ksplit) {
    constexpr int LDA = 40;
    constexpr int LDBN = 136;
    __shared__ alignas(16) __nv_bfloat16 Ah[128 * LDA], Al[128 * LDA];
    __shared__ alignas(16) __nv_bfloat16 Bh[128 * LDA], Bl[128 * LDA];
    int tid = threadIdx.x;
    int bm = blockIdx.y * 128, bn = blockIdx.x * 128;
    int kchunk = K / ksplit, k0 = blockIdx.z * kchunk, kend = k0 + kchunk;
    C += (size_t)blockIdx.z * M * N;
    int lr = tid >> 2, lc = (tid & 3) * 4;
    int brow = tid >> 5, bcol = (tid & 31) * 4;

    float4 pa[2], pb[2];
    auto loadA = [&](int kk) {
        #pragma unroll
        for (int h = 0; h < 2; h++)
            pa[h] = *(const float4*)(A + (size_t)(bm + lr + h * 64) * K + kk + lc);
    };
    auto loadB = [&](int kk) {
        if (GATHER) {
            #pragma unroll
            for (int h = 0; h < 2; h++) {
                int n = bn + lr + h * 64;
                int combo = n >> 9, c = n & 511;
                int ki = combo >> 2, kj = combo & 3;
                float v[4];
                #pragma unroll
                for (int t = 0; t < 4; t++) {
                    int p = kk + lc + t;
                    int py = p >> 4, px = p & 15;
                    int r = 2 * py + ki - 1, col = 2 * px + kj - 1;
                    v[t] = ((unsigned)r < 32u && (unsigned)col < 32u)
                         ? B[c * 1024 + r * 32 + col] : 0.f;
                }
                pb[h] = make_float4(v[0], v[1], v[2], v[3]);
            }
        } else if (BT) {
            #pragma unroll
            for (int h = 0; h < 2; h++)
                pb[h] = *(const float4*)(B + (size_t)(bn + lr + h * 64) * K + kk + lc);
        } else {
            #pragma unroll
            for (int h = 0; h < 2; h++)
                pb[h] = *(const float4*)(B + (size_t)(kk + brow + h * 8) * N + bn + bcol);
        }
    };
    auto split2 = [](__nv_bfloat16* hp, __nv_bfloat16* lp, float v0, float v1) {
        __nv_bfloat16 h0 = __float2bfloat16(v0), h1 = __float2bfloat16(v1);
        *reinterpret_cast<__nv_bfloat162*>(hp) = __halves2bfloat162(h0, h1);
        __nv_bfloat16 l0 = __float2bfloat16(v0 - __bfloat162float(h0));
        __nv_bfloat16 l1 = __float2bfloat16(v1 - __bfloat162float(h1));
        *reinterpret_cast<__nv_bfloat162*>(lp) = __halves2bfloat162(l0, l1);
    };
    auto storeTiles = [&]() {
        #pragma unroll
        for (int h = 0; h < 2; h++) {
            int m = lr + h * 64;
            int idx = m * LDA + lc;
            split2(&Ah[idx], &Al[idx], pa[h].x, pa[h].y);
            split2(&Ah[idx + 2], &Al[idx + 2], pa[h].z, pa[h].w);
        }
        if (BT || GATHER) {
            #pragma unroll
            for (int h = 0; h < 2; h++) {
                int n = lr + h * 64;
                int idx = n * LDA + lc;
                split2(&Bh[idx], &Bl[idx], pb[h].x, pb[h].y);
                split2(&Bh[idx + 2], &Bl[idx + 2], pb[h].z, pb[h].w);
            }
        } else {
            #pragma unroll
            for (int h = 0; h < 2; h++) {
                int idx = (brow + h * 8) * LDBN + bcol;
                split2(&Bh[idx], &Bl[idx], pb[h].x, pb[h].y);
                split2(&Bh[idx + 2], &Bl[idx + 2], pb[h].z, pb[h].w);
            }
        }
    };

    int warp = tid >> 5;
    int wm = warp & 3, wn = warp >> 2;
    wmma::fragment<wmma::accumulator, 16, 16, 16, float> cf[2][4];
    #pragma unroll
    for (int i = 0; i < 2; i++)
        #pragma unroll
        for (int j = 0; j < 4; j++) wmma::fill_fragment(cf[i][j], 0.f);

    loadA(k0); loadB(k0);
    for (int kk = k0; kk < kend; kk += 16) {
        storeTiles();
        __syncthreads();
        if (kk + 16 < kend) { loadA(kk + 16); loadB(kk + 16); }
        wmma::fragment<wmma::matrix_a, 16, 16, 16, __nv_bfloat16, wmma::row_major> afh[2], afl[2];
        #pragma unroll
        for (int i = 0; i < 2; i++) {
            int m0 = wm * 32 + i * 16;
            wmma::load_matrix_sync(afh[i], &Ah[m0 * LDA], LDA);
            wmma::load_matrix_sync(afl[i], &Al[m0 * LDA], LDA);
        }
        if (BT || GATHER) {
            wmma::fragment<wmma::matrix_b, 16, 16, 16, __nv_bfloat16, wmma::col_major> bfh[4], bfl[4];
            #pragma unroll
            for (int j = 0; j < 4; j++) {
                int n0 = wn * 64 + j * 16;
                wmma::load_matrix_sync(bfh[j], &Bh[n0 * LDA], LDA);
                wmma::load_matrix_sync(bfl[j], &Bl[n0 * LDA], LDA);
            }
            #pragma unroll
            for (int i = 0; i < 2; i++)
                #pragma unroll
                for (int j = 0; j < 4; j++) {
                    wmma::mma_sync(cf[i][j], afh[i], bfh[j], cf[i][j]);
                    wmma::mma_sync(cf[i][j], afh[i], bfl[j], cf[i][j]);
                    wmma::mma_sync(cf[i][j], afl[i], bfh[j], cf[i][j]);
                }
        } else {
            wmma::fragment<wmma::matrix_b, 16, 16, 16, __nv_bfloat16, wmma::row_major> bfh[4], bfl[4];
            #pragma unroll
            for (int j = 0; j < 4; j++) {
                int n0 = wn * 64 + j * 16;
                wmma::load_matrix_sync(bfh[j], &Bh[n0], LDBN);
                wmma::load_matrix_sync(bfl[j], &Bl[n0], LDBN);
            }
            #pragma unroll
            for (int i = 0; i < 2; i++)
                #pragma unroll
                for (int j = 0; j < 4; j++) {
                    wmma::mma_sync(cf[i][j], afh[i], bfh[j], cf[i][j]);
                    wmma::mma_sync(cf[i][j], afh[i], bfl[j], cf[i][j]);
                    wmma::mma_sync(cf[i][j], afl[i], bfh[j], cf[i][j]);
                }
        }
        __syncthreads();
    }
    #pragma unroll
    for (int i = 0; i < 2; i++)
        #pragma unroll
        for (int j = 0; j < 4; j++) {
            int row = bm + wm * 32 + i * 16;
            int col = bn + wn * 64 + j * 16;
            wmma::store_matrix_sync(C + (size_t)row * N + col, cf[i][j], N, wmma::mem_row_major);
        }
}

// ---------------- reduce npart split-K slices ----------------
__global__ __launch_bounds__(256) void reduceN_kernel(const float* __restrict__ in,
                                                      float* __restrict__ out,
                                                      int n, int npart) {
    int i = blockIdx.x * 256 + threadIdx.x;
    float s = in[i];
    for (int z = 1; z < npart; z++) s += in[(size_t)z * n + i];
    out[i] = s;
}

// ------ 6) fused score reconstruction (9-tap sum of R) + softmax; pnorm inline ------
__global__ __launch_bounds__(256) void score_softmax_kernel() {
    int q = blockIdx.x;
    int qy = q >> 4, qx = q & 15;
    __shared__ float sr[9][256];
    __shared__ float red[256];
    int tid = threadIdx.x;
    int p = tid, py = p >> 4, px = p & 15;
    float ss = 0.f;
    #pragma unroll
    for (int ij = 0; ij < 9; ij++) {
        int di = ij / 3 - 1, dj = ij % 3 - 1;
        int y = py + di, x = px + dj;
        if ((unsigned)y < 16u && (unsigned)x < 16u) {
            int u = y * 16 + x;
            ss += g_R[u * 256 + u];
        }
    }
    float norm = fmaxf(sqrtf(ss), 1e-4f);
    #pragma unroll
    for (int ij = 0; ij < 9; ij++) {
        int di = ij / 3 - 1, dj = ij % 3 - 1;
        int y = qy + di, x = qx + dj;
        sr[ij][tid] = ((unsigned)y < 16u && (unsigned)x < 16u)
                    ? g_R[(y * 16 + x) * 256 + tid] : 0.f;
    }
    __syncthreads();
    float v = 0.f;
    #pragma unroll
    for (int ij = 0; ij < 9; ij++) {
        int di = ij / 3 - 1, dj = ij % 3 - 1;
        int y = py + di, x = px + dj;
        if ((unsigned)y < 16u && (unsigned)x < 16u) v += sr[ij][y * 16 + x];
    }
    v = v * 10.f / norm;
    red[p] = v; __syncthreads();
    for (int s = 128; s > 0; s >>= 1) { if (p < s) red[p] = fmaxf(red[p], red[p + s]); __syncthreads(); }
    float mx = red[0]; __syncthreads();
    float e = __expf(v - mx);
    red[p] = e; __syncthreads();
    for (int s = 128; s > 0; s >>= 1) { if (p < s) red[p] += red[p + s]; __syncthreads(); }
    float inv = 1.f / red[0];
    g_attnT[q * 256 + p] = e * inv;
}

// ---------------- 9) scatter deconv taps -> out_32 pixel-major ----------------
__global__ __launch_bounds__(512) void ral_out_kernel() {
    int pix = blockIdx.x;
    int ho = pix >> 5, wo = pix & 31;
    int c = threadIdx.x;
    float acc = 0.f;
    for (int ki = (ho + 1) & 1; ki < 4; ki += 2) {
        int qy = (ho + 1 - ki) >> 1;
        if ((unsigned)qy >= 16u) continue;
        for (int kj = (wo + 1) & 1; kj < 4; kj += 2) {
            int qx = (wo + 1 - kj) >> 1;
            if ((unsigned)qx >= 16u) continue;
            int q = qy * 16 + qx;
            acc += g_T[(size_t)q * 8192 + (ki * 4 + kj) * 512 + c];
        }
    }
    g_out32T[(size_t)pix * 512 + c] = acc * 0.25f;
}

// ------ 10a) separable gaussian stage 1 ------
__global__ __launch_bounds__(128) void gauss1_kernel() {
    int y = blockIdx.x;
    int cc = blockIdx.y;
    int c = cc * 128 + threadIdx.x;
    __shared__ float gxs[32 * 32];
    for (int e = threadIdx.x; e < 1024; e += 128) {
        int i = e >> 5, xx = e & 31;
        float d = (float)(xx - i);
        gxs[e] = __expf(-d * d * (1.f / 4.5f));
    }
    __syncthreads();
    float vals[32];
    #pragma unroll
    for (int xx = 0; xx < 32; xx++)
        vals[xx] = g_out32T[(size_t)(xx * 32 + y) * 512 + c];
    for (int i = 0; i < 32; i++) {
        float acc = 0.f;
        const float* gr = &gxs[i * 32];
        #pragma unroll
        for (int xx = 0; xx < 32; xx++) acc += gr[xx] * vals[xx];
        g_T[(size_t)(i * 32 + y) * 512 + c] = acc;
    }
}

// ------ 10b) stage 2 ------
__global__ __launch_bounds__(128) void gauss2_kernel() {
    int i = blockIdx.x;
    int cc = blockIdx.y;
    int c = cc * 128 + threadIdx.x;
    const float scale = 1.f / (2.f * 3.14159265358979323846f * 2.25f);
    __shared__ float gys[32 * 32];
    for (int e = threadIdx.x; e < 1024; e += 128) {
        int k = e >> 5, yy = e & 31;
        float d = (float)(yy - k);
        gys[e] = __expf(-d * d * (1.f / 4.5f));
    }
    __syncthreads();
    float vals[32];
    #pragma unroll
    for (int yy = 0; yy < 32; yy++)
        vals[yy] = g_T[(size_t)(i * 32 + yy) * 512 + c];
    for (int k = 0; k < 32; k++) {
        float acc = 0.f;
        const float* gr = &gys[k * 32];
        #pragma unroll
        for (int yy = 0; yy < 32; yy++) acc += gr[yy] * vals[yy];
        g_z[(size_t)(i * 32 + k) * 512 + c] = acc * scale;
    }
}

// ---------------- 11) CSA (inline sigmoids — confirmed fastest) ----------------
__global__ __launch_bounds__(512) void csa_kernel() {
    int pos = blockIdx.x;
    int y = pos >> 5, x = pos & 31;
    int c = threadIdx.x;
    __shared__ float s_sum[16 * 9];
    __shared__ float s_a[9];
    float center = g_out32T[(size_t)pos * 512 + c];
    float sc = 1.f / (1.f + __expf(-center));
    float nb[9], pr[9];
    #pragma unroll
    for (int ij = 0; ij < 9; ij++) {
        int di = ij / 3 - 1, dj = ij % 3 - 1;
        int yy = y + di, xx = x + dj;
        bool ok = (unsigned)yy < 32u && (unsigned)xx < 32u;
        float v = ok ? g_out32T[(size_t)(yy * 32 + xx) * 512 + c] : 0.f;
        nb[ij] = v;
        float sn = ok ? 1.f / (1.f + __expf(-v)) : 0.f;
        pr[ij] = sc * sn;
    }
    #pragma unroll
    for (int ij = 0; ij < 9; ij++)
        #pragma unroll
        for (int o = 16; o > 0; o >>= 1) pr[ij] += __shfl_down_sync(0xFFFFFFFFu, pr[ij], o);
    int w = c >> 5, l = c & 31;
    if (l == 0) {
        #pragma unroll
        for (int ij = 0; ij < 9; ij++) s_sum[w * 9 + ij] = pr[ij];
    }
    __syncthreads();
    if (c < 9) {
        float t = 0.f;
        for (int w2 = 0; w2 < 16; w2++) t += s_sum[w2 * 9 + c];
        s_a[c] = t * (1.f / 512.f);
    }
    __syncthreads();
    if (c == 0) {
        float mx = s_a[0];
        for (int ij = 1; ij < 9; ij++) mx = fmaxf(mx, s_a[ij]);
        float sum = 0.f; float e[9];
        for (int ij = 0; ij < 9; ij++) { e[ij] = __expf(s_a[ij] - mx); sum += e[ij]; }
        float invs = 1.f / sum;
        for (int ij = 0; ij < 9; ij++) s_a[ij] = e[ij] * invs;
    }
    __syncthreads();
    float out = 0.f;
    #pragma unroll
    for (int ij = 0; ij < 9; ij++) out += s_a[ij] * nb[ij];
    g_z[512 * 1024 + (size_t)pos * 512 + c] = out;
}

// ------------- instance norm + leaky relu; sums npart slices; optional concat copy ----
__global__ __launch_bounds__(256) void norm_leaky_kernel(
    const float* __restrict__ in, int npart, float* __restrict__ outA,
    const float* __restrict__ cpsrc, float* __restrict__ outB) {
    __shared__ float s_red[64];
    int c = blockIdx.x, tid = threadIdx.x;
    float v[4]; float s = 0.f, s2 = 0.f;
    #pragma unroll
    for (int q = 0; q < 4; q++) {
        int idx = c * 1024 + tid + q * 256;
        float acc = in[idx];
        for (int z = 1; z < npart; z++) acc += in[(size_t)z * 512 * 1024 + idx];
        v[q] = acc;
        s += acc; s2 += acc * acc;
    }
    blockReduce2(s, s2, s_red);
    float mu = s * (1.f / 1024.f);
    float inv = rsqrtf(s2 * (1.f / 1024.f) - mu * mu + 1e-5f);
    #pragma unroll
    for (int q = 0; q < 4; q++) {
        float f = (v[q] - mu) * inv;
        outA[c * 1024 + tid + q * 256] = f >= 0.f ? f : 0.2f * f;
    }
    if (cpsrc != nullptr) {
        #pragma unroll
        for (int q = 0; q < 4; q++)
            outB[c * 1024 + tid + q * 256] = cpsrc[c * 1024 + tid + q * 256];
    }
}

// ---------------- host ----------------
extern "C" void kernel_launch(void* const* d_in, const int* in_sizes, int n_in,
                              void* d_out, int out_size) {
    const float* x     = (const float*)d_in[0];
    const float* w_sk3 = (const float*)d_in[2];
    const float* w_sk5 = (const float*)d_in[4];
    const float* w_sk7 = (const float*)d_in[6];
    const float* w_fc  = (const float*)d_in[8];
    const float* b_fc  = (const float*)d_in[9];
    const float* w_fc0 = (const float*)d_in[10];
    const float* b_fc0 = (const float*)d_in[11];
    const float* w_fc1 = (const float*)d_in[12];
    const float* b_fc1 = (const float*)d_in[13];
    const float* w_fc2 = (const float*)d_in[14];
    const float* b_fc2 = (const float*)d_in[15];
    const float* w_down = (const float*)d_in[16];
    const float* w_fuse = (const float*)d_in[17];

    float *fgsT, *S, *R, *attnT, *T, *z, *d1, *z2, *outres;
    cudaGetSymbolAddress((void**)&fgsT, g_fgsT);
    cudaGetSymbolAddress((void**)&S, g_S);
    cudaGetSymbolAddress((void**)&R, g_R);
    cudaGetSymbolAddress((void**)&attnT, g_attnT);
    cudaGetSymbolAddress((void**)&T, g_T);
    cudaGetSymbolAddress((void**)&z, g_z);
    cudaGetSymbolAddress((void**)&d1, g_d1);
    cudaGetSymbolAddress((void**)&z2, g_z2);
    cudaGetSymbolAddress((void**)&outres, g_outres);

    // SKConv via tensor cores (fused IN + relu + bsum; bias cancels under IN)
    cudaFuncSetAttribute(sk_mma_all, cudaFuncAttributeMaxDynamicSharedMemorySize, SMEM_SK);
    sk_mma_all<<<dim3(32, 3), 512, SMEM_SK>>>(x, w_sk3, w_sk5, w_sk7);
    fz_kernel<<<32, 256>>>(w_fc, b_fc);
    combine_kernel<<<512, 256>>>(w_fc0, b_fc0, w_fc1, b_fc1, w_fc2, b_fc2);
    // RAL Gram matrix R = F F^T (fp32, 64x64 tiles, k-tile 16, split-K 8)
    gemm64_nt<<<dim3(4, 4, 8), 256>>>(fgsT, S, 256, 512, 8);
    reduceN_kernel<<<256, 256>>>(S, R, 256 * 256, 8);
    score_softmax_kernel<<<256, 256>>>();
    // deconv-as-GEMM (bf16x2): T' = attnT * gather(bg)^T
    gemm128_bf16<true, true><<<dim3(64, 2, 1), 256>>>(attnT, outres, T, 256, 8192, 256, 1);
    ral_out_kernel<<<1024, 512>>>();
    // separable gaussian -> first half of z
    gauss1_kernel<<<dim3(32, 4), 128>>>();
    gauss2_kernel<<<dim3(32, 4), 128>>>();
    // CSA -> second half of z
    csa_kernel<<<1024, 512>>>();
    // down 1x1 conv (bf16x2, split-K 4) + IN + leaky, concat out_res
    gemm128_bf16<false, false><<<dim3(8, 4, 4), 256>>>(w_down, z, d1, 512, 1024, 1024, 4);
    norm_leaky_kernel<<<512, 256>>>(d1, 4, z2, outres, z2 + 512 * 1024);
    // fuse 1x1 conv (bf16x2, split-K 4) + IN + leaky -> output
    gemm128_bf16<false, false><<<dim3(8, 4, 4), 256>>>(w_fuse, z2, d1, 512, 1024, 1024, 4);
    norm_leaky_kernel<<<512, 256>>>(d1, 4, (float*)d_out, nullptr, nullptr);
}

// round 14
// speedup vs baseline: 1.0377x; 1.0377x over previous
#include <cuda_runtime.h>
#include <cuda_bf16.h>
#include <mma.h>
#include <cstddef>

using namespace nvcuda;

// ---------------- scratch (static __device__, no allocs) ----------------
__device__ float g_feas[3 * 512 * 1024];
__device__ float g_bsum[3 * 512];
__device__ float g_fz[32];
__device__ float g_outres[512 * 1024];
__device__ float g_fgsT[256 * 512];       // fg_small, pixel-major [pos][c]
__device__ float g_S[8 * 256 * 256];      // split-K partials of R = F F^T
__device__ float g_R[256 * 256];          // reduced R
__device__ float g_attnT[256 * 256];      // attn transposed: [q][p]
__device__ float g_T[256 * 8192];         // T'[q][row]; reused for gaussian stage-1
__device__ float g_out32T[1024 * 512];    // post-RAL out_32, pixel-major
__device__ float g_z[1024 * 1024];        // concat(gus_out, out_csa)
__device__ float g_d1[4 * 512 * 1024];    // split-K partials of down/fuse
__device__ float g_z2[1024 * 1024];       // concat(leaky(norm(down)), out_res)

// ---------------- helpers ----------------
__device__ __forceinline__ void blockReduce2(float& s, float& s2, float* sm) {
    __syncthreads();
    int tid = threadIdx.x;
    #pragma unroll
    for (int o = 16; o > 0; o >>= 1) {
        s  += __shfl_down_sync(0xFFFFFFFFu, s, o);
        s2 += __shfl_down_sync(0xFFFFFFFFu, s2, o);
    }
    int w = tid >> 5, l = tid & 31;
    int nw = blockDim.x >> 5;
    if (l == 0) { sm[w] = s; sm[32 + w] = s2; }
    __syncthreads();
    if (tid < 32) {
        s  = (tid < nw) ? sm[tid] : 0.f;
        s2 = (tid < nw) ? sm[32 + tid] : 0.f;
        #pragma unroll
        for (int o = 16; o > 0; o >>= 1) {
            s  += __shfl_down_sync(0xFFFFFFFFu, s, o);
            s2 += __shfl_down_sync(0xFFFFFFFFu, s2, o);
        }
        if (tid == 0) { sm[0] = s; sm[32] = s2; }
    }
    __syncthreads();
    s = sm[0]; s2 = sm[32];
}

// ------- 1) SK grouped conv: 128 thr, 8 px/thread, pipelined ic tiles (R11 scalar) -------
template <int KS>
__device__ __forceinline__ void sk_conv_impl(
    const float* __restrict__ x, const float* __restrict__ w,
    const float* __restrict__ bias, int branch,
    float* s_ch, float* s_w, float* s_red) {
    constexpr int PAD = KS / 2;
    constexpr int W = 32 + 2 * PAD;
    int oc = blockIdx.x;
    int tid = threadIdx.x;
    int y = tid >> 2, xq = (tid & 3) * 8;
    const float* xin = x + (size_t)(oc >> 4) * 16 * 1024;
    const float* wo = w + (size_t)oc * 16 * KS * KS;
    for (int i = tid; i < 16 * KS * KS; i += 128) s_w[i] = wo[i];
    for (int i = tid; i < W * W; i += 128) s_ch[i] = 0.f;

    float pre[8];
    #pragma unroll
    for (int j = 0; j < 8; j++) pre[j] = xin[tid + j * 128];

    float acc[8] = {0.f, 0.f, 0.f, 0.f, 0.f, 0.f, 0.f, 0.f};
    for (int ic = 0; ic < 16; ic++) {
        __syncthreads();
        #pragma unroll
        for (int j = 0; j < 8; j++) {
            int i = tid + j * 128;
            int yy = i >> 5, xx = i & 31;
            s_ch[(yy + PAD) * W + xx + PAD] = pre[j];
        }
        __syncthreads();
        if (ic < 15) {
            #pragma unroll
            for (int j = 0; j < 8; j++) pre[j] = xin[(ic + 1) * 1024 + tid + j * 128];
        }
        const float* wi = &s_w[ic * KS * KS];
        #pragma unroll
        for (int ky = 0; ky < KS; ky++) {
            const float* rowp = &s_ch[(y + ky) * W + xq];
            float r[KS + 7];
            #pragma unroll
            for (int j = 0; j < KS + 7; j++) r[j] = rowp[j];
            #pragma unroll
            for (int kx = 0; kx < KS; kx++) {
                float wv = wi[ky * KS + kx];
                #pragma unroll
                for (int t = 0; t < 8; t++) acc[t] += r[kx + t] * wv;
            }
        }
    }
    float b = bias[oc];
    float s = 0.f, s2 = 0.f;
    #pragma unroll
    for (int t = 0; t < 8; t++) { acc[t] += b; s += acc[t]; s2 += acc[t] * acc[t]; }
    blockReduce2(s, s2, s_red);
    float mu = s * (1.f / 1024.f);
    float var = s2 * (1.f / 1024.f) - mu * mu;
    float inv = rsqrtf(var + 1e-5f);
    float rs = 0.f;
    float* fo = &g_feas[(size_t)branch * 512 * 1024 + (size_t)oc * 1024];
    float rv[8];
    #pragma unroll
    for (int t = 0; t < 8; t++) {
        float r = (acc[t] - mu) * inv;
        r = fmaxf(r, 0.f);
        rv[t] = r;
        rs += r;
    }
    *(float4*)(fo + y * 32 + xq)     = make_float4(rv[0], rv[1], rv[2], rv[3]);
    *(float4*)(fo + y * 32 + xq + 4) = make_float4(rv[4], rv[5], rv[6], rv[7]);
    float dummy = 0.f;
    blockReduce2(rs, dummy, s_red);
    if (tid == 0) g_bsum[branch * 512 + oc] = rs;
}

__global__ __launch_bounds__(128) void sk_conv_all(
    const float* __restrict__ x,
    const float* __restrict__ w3, const float* __restrict__ b3,
    const float* __restrict__ w5, const float* __restrict__ b5,
    const float* __restrict__ w7, const float* __restrict__ b7) {
    __shared__ float s_ch[38 * 38];
    __shared__ float s_w[16 * 49];
    __shared__ float s_red[64];
    int br = blockIdx.y;
    if (br == 0)      sk_conv_impl<3>(x, w3, b3, 0, s_ch, s_w, s_red);
    else if (br == 1) sk_conv_impl<5>(x, w5, b5, 1, s_ch, s_w, s_red);
    else              sk_conv_impl<7>(x, w7, b7, 2, s_ch, s_w, s_red);
}

// ---------------- 2) FC1 ----------------
__global__ __launch_bounds__(256) void fz_kernel(
    const float* __restrict__ w_fc, const float* __restrict__ b_fc) {
    __shared__ float s_red[64];
    int j = blockIdx.x, tid = threadIdx.x;
    float s = 0.f;
    for (int c = tid; c < 512; c += 256) {
        float fs = (g_bsum[c] + g_bsum[512 + c] + g_bsum[1024 + c]) * (1.f / 1024.f);
        s += fs * w_fc[j * 512 + c];
    }
    float dummy = 0.f;
    blockReduce2(s, dummy, s_red);
    if (tid == 0) g_fz[j] = s + b_fc[j];
}

// ------- 3) per-channel branch attention + combine -> out_res; avg pool -> fgsT ------
__global__ __launch_bounds__(256) void combine_kernel(
    const float* __restrict__ w0, const float* __restrict__ b0,
    const float* __restrict__ w1, const float* __restrict__ b1,
    const float* __restrict__ w2, const float* __restrict__ b2) {
    int c = blockIdx.x, tid = threadIdx.x;
    __shared__ float s_fz[32];
    __shared__ float s_a[3];
    __shared__ float s_o[1024];
    if (tid < 32) s_fz[tid] = g_fz[tid];
    __syncthreads();
    int w = tid >> 5, l = tid & 31;
    if (w < 3) {
        const float* wt = (w == 0) ? w0 : (w == 1) ? w1 : w2;
        const float* bt = (w == 0) ? b0 : (w == 1) ? b1 : b2;
        float v = s_fz[l] * wt[c * 32 + l];
        #pragma unroll
        for (int o = 16; o > 0; o >>= 1) v += __shfl_down_sync(0xFFFFFFFFu, v, o);
        if (l == 0) s_a[w] = v + bt[c];
    }
    __syncthreads();
    float A0 = s_a[0], A1 = s_a[1], A2 = s_a[2];
    float mx = fmaxf(A0, fmaxf(A1, A2));
    float e0 = __expf(A0 - mx), e1 = __expf(A1 - mx), e2 = __expf(A2 - mx);
    float inv = 1.f / (e0 + e1 + e2);
    float a0 = e0 * inv, a1 = e1 * inv, a2 = e2 * inv;

    for (int i = tid; i < 1024; i += 256) {
        float v = a0 * g_feas[(size_t)c * 1024 + i]
                + a1 * g_feas[512 * 1024 + (size_t)c * 1024 + i]
                + a2 * g_feas[2 * 512 * 1024 + (size_t)c * 1024 + i];
        g_outres[c * 1024 + i] = v;
        s_o[i] = v;
    }
    __syncthreads();
    int py = tid >> 4, px = tid & 15;
    float p = 0.25f * (s_o[(2 * py) * 32 + 2 * px] + s_o[(2 * py) * 32 + 2 * px + 1] +
                       s_o[(2 * py + 1) * 32 + 2 * px] + s_o[(2 * py + 1) * 32 + 2 * px + 1]);
    g_fgsT[(size_t)tid * 512 + c] = p;
}

// ---- fp32 64x64-tile NT SGEMM for R = F F^T (k-tile 16, split-K) ----
__global__ __launch_bounds__(256) void gemm64_nt(
    const float* __restrict__ A, float* __restrict__ C,
    int M, int K, int ksplit) {
    __shared__ float As[16][68];
    __shared__ float Bs[16][68];
    int tid = threadIdx.x;
    int bm = blockIdx.y * 64, bn = blockIdx.x * 64;
    int kchunk = K / ksplit, k0 = blockIdx.z * kchunk, kend = k0 + kchunk;
    C += (size_t)blockIdx.z * M * M;
    int lr = tid >> 2, lc = (tid & 3) * 4;
    int tx = tid & 15, ty = tid >> 4;

    float4 pa, pb;
    auto loadAB = [&](int kk) {
        pa = *(const float4*)(A + (size_t)(bm + lr) * K + kk + lc);
        pb = *(const float4*)(A + (size_t)(bn + lr) * K + kk + lc);
    };
    auto storeTiles = [&]() {
        As[lc][lr] = pa.x; As[lc + 1][lr] = pa.y; As[lc + 2][lr] = pa.z; As[lc + 3][lr] = pa.w;
        Bs[lc][lr] = pb.x; Bs[lc + 1][lr] = pb.y; Bs[lc + 2][lr] = pb.z; Bs[lc + 3][lr] = pb.w;
    };

    float acc[4][4] = {};
    loadAB(k0);
    for (int kk = k0; kk < kend; kk += 16) {
        storeTiles();
        __syncthreads();
        if (kk + 16 < kend) loadAB(kk + 16);
        #pragma unroll
        for (int k = 0; k < 16; k++) {
            float4 a = *(const float4*)&As[k][ty * 4];
            float4 b = *(const float4*)&Bs[k][tx * 4];
            float ar[4] = {a.x, a.y, a.z, a.w};
            float br[4] = {b.x, b.y, b.z, b.w};
            #pragma unroll
            for (int i = 0; i < 4; i++)
                #pragma unroll
                for (int j = 0; j < 4; j++) acc[i][j] += ar[i] * br[j];
        }
        __syncthreads();
    }
    #pragma unroll
    for (int i = 0; i < 4; i++)
        *(float4*)(C + (size_t)(bm + ty * 4 + i) * M + bn + tx * 4) =
            make_float4(acc[i][0], acc[i][1], acc[i][2], acc[i][3]);
}

// ---- bf16x2-split WMMA 128x128-tile GEMM (3-mma Ootomo) ----
template <bool BT, bool GATHER>
__global__ __launch_bounds__(256) void gemm128_bf16(
    const float* __restrict__ A, const float* __restrict__ B, float* __restrict__ C,
    int M, int N, int K, int ksplit) {
    constexpr int LDA = 40;
    constexpr int LDBN = 136;
    __shared__ alignas(16) __nv_bfloat16 Ah[128 * LDA], Al[128 * LDA];
    __shared__ alignas(16) __nv_bfloat16 Bh[128 * LDA], Bl[128 * LDA];
    int tid = threadIdx.x;
    int bm = blockIdx.y * 128, bn = blockIdx.x * 128;
    int kchunk = K / ksplit, k0 = blockIdx.z * kchunk, kend = k0 + kchunk;
    C += (size_t)blockIdx.z * M * N;
    int lr = tid >> 2, lc = (tid & 3) * 4;
    int brow = tid >> 5, bcol = (tid & 31) * 4;

    float4 pa[2], pb[2];
    auto loadA = [&](int kk) {
        #pragma unroll
        for (int h = 0; h < 2; h++)
            pa[h] = *(const float4*)(A + (size_t)(bm + lr + h * 64) * K + kk + lc);
    };
    auto loadB = [&](int kk) {
        if (GATHER) {
            #pragma unroll
            for (int h = 0; h < 2; h++) {
                int n = bn + lr + h * 64;
                int combo = n >> 9, c = n & 511;
                int ki = combo >> 2, kj = combo & 3;
                float v[4];
                #pragma unroll
                for (int t = 0; t < 4; t++) {
                    int p = kk + lc + t;
                    int py = p >> 4, px = p & 15;
                    int r = 2 * py + ki - 1, col = 2 * px + kj - 1;
                    v[t] = ((unsigned)r < 32u && (unsigned)col < 32u)
                         ? B[c * 1024 + r * 32 + col] : 0.f;
                }
                pb[h] = make_float4(v[0], v[1], v[2], v[3]);
            }
        } else if (BT) {
            #pragma unroll
            for (int h = 0; h < 2; h++)
                pb[h] = *(const float4*)(B + (size_t)(bn + lr + h * 64) * K + kk + lc);
        } else {
            #pragma unroll
            for (int h = 0; h < 2; h++)
                pb[h] = *(const float4*)(B + (size_t)(kk + brow + h * 8) * N + bn + bcol);
        }
    };
    auto split2 = [](__nv_bfloat16* hp, __nv_bfloat16* lp, float v0, float v1) {
        __nv_bfloat16 h0 = __float2bfloat16(v0), h1 = __float2bfloat16(v1);
        *reinterpret_cast<__nv_bfloat162*>(hp) = __halves2bfloat162(h0, h1);
        __nv_bfloat16 l0 = __float2bfloat16(v0 - __bfloat162float(h0));
        __nv_bfloat16 l1 = __float2bfloat16(v1 - __bfloat162float(h1));
        *reinterpret_cast<__nv_bfloat162*>(lp) = __halves2bfloat162(l0, l1);
    };
    auto storeTiles = [&]() {
        #pragma unroll
        for (int h = 0; h < 2; h++) {
            int m = lr + h * 64;
            int idx = m * LDA + lc;
            split2(&Ah[idx], &Al[idx], pa[h].x, pa[h].y);
            split2(&Ah[idx + 2], &Al[idx + 2], pa[h].z, pa[h].w);
        }
        if (BT || GATHER) {
            #pragma unroll
            for (int h = 0; h < 2; h++) {
                int n = lr + h * 64;
                int idx = n * LDA + lc;
                split2(&Bh[idx], &Bl[idx], pb[h].x, pb[h].y);
                split2(&Bh[idx + 2], &Bl[idx + 2], pb[h].z, pb[h].w);
            }
        } else {
            #pragma unroll
            for (int h = 0; h < 2; h++) {
                int idx = (brow + h * 8) * LDBN + bcol;
                split2(&Bh[idx], &Bl[idx], pb[h].x, pb[h].y);
                split2(&Bh[idx + 2], &Bl[idx + 2], pb[h].z, pb[h].w);
            }
        }
    };

    int warp = tid >> 5;
    int wm = warp & 3, wn = warp >> 2;
    wmma::fragment<wmma::accumulator, 16, 16, 16, float> cf[2][4];
    #pragma unroll
    for (int i = 0; i < 2; i++)
        #pragma unroll
        for (int j = 0; j < 4; j++) wmma::fill_fragment(cf[i][j], 0.f);

    loadA(k0); loadB(k0);
    for (int kk = k0; kk < kend; kk += 16) {
        storeTiles();
        __syncthreads();
        if (kk + 16 < kend) { loadA(kk + 16); loadB(kk + 16); }
        wmma::fragment<wmma::matrix_a, 16, 16, 16, __nv_bfloat16, wmma::row_major> afh[2], afl[2];
        #pragma unroll
        for (int i = 0; i < 2; i++) {
            int m0 = wm * 32 + i * 16;
            wmma::load_matrix_sync(afh[i], &Ah[m0 * LDA], LDA);
            wmma::load_matrix_sync(afl[i], &Al[m0 * LDA], LDA);
        }
        if (BT || GATHER) {
            wmma::fragment<wmma::matrix_b, 16, 16, 16, __nv_bfloat16, wmma::col_major> bfh[4], bfl[4];
            #pragma unroll
            for (int j = 0; j < 4; j++) {
                int n0 = wn * 64 + j * 16;
                wmma::load_matrix_sync(bfh[j], &Bh[n0 * LDA], LDA);
                wmma::load_matrix_sync(bfl[j], &Bl[n0 * LDA], LDA);
            }
            #pragma unroll
            for (int i = 0; i < 2; i++)
                #pragma unroll
                for (int j = 0; j < 4; j++) {
                    wmma::mma_sync(cf[i][j], afh[i], bfh[j], cf[i][j]);
                    wmma::mma_sync(cf[i][j], afh[i], bfl[j], cf[i][j]);
                    wmma::mma_sync(cf[i][j], afl[i], bfh[j], cf[i][j]);
                }
        } else {
            wmma::fragment<wmma::matrix_b, 16, 16, 16, __nv_bfloat16, wmma::row_major> bfh[4], bfl[4];
            #pragma unroll
            for (int j = 0; j < 4; j++) {
                int n0 = wn * 64 + j * 16;
                wmma::load_matrix_sync(bfh[j], &Bh[n0], LDBN);
                wmma::load_matrix_sync(bfl[j], &Bl[n0], LDBN);
            }
            #pragma unroll
            for (int i = 0; i < 2; i++)
                #pragma unroll
                for (int j = 0; j < 4; j++) {
                    wmma::mma_sync(cf[i][j], afh[i], bfh[j], cf[i][j]);
                    wmma::mma_sync(cf[i][j], afh[i], bfl[j], cf[i][j]);
                    wmma::mma_sync(cf[i][j], afl[i], bfh[j], cf[i][j]);
                }
        }
        __syncthreads();
    }
    #pragma unroll
    for (int i = 0; i < 2; i++)
        #pragma unroll
        for (int j = 0; j < 4; j++) {
            int row = bm + wm * 32 + i * 16;
            int col = bn + wn * 64 + j * 16;
            wmma::store_matrix_sync(C + (size_t)row * N + col, cf[i][j], N, wmma::mem_row_major);
        }
}

// ---------------- reduce npart split-K slices ----------------
__global__ __launch_bounds__(256) void reduceN_kernel(const float* __restrict__ in,
                                                      float* __restrict__ out,
                                                      int n, int npart) {
    int i = blockIdx.x * 256 + threadIdx.x;
    float s = in[i];
    for (int z = 1; z < npart; z++) s += in[(size_t)z * n + i];
    out[i] = s;
}

// ------ 6) fused score reconstruction (9-tap sum of R) + softmax; pnorm inline ------
__global__ __launch_bounds__(256) void score_softmax_kernel() {
    int q = blockIdx.x;
    int qy = q >> 4, qx = q & 15;
    __shared__ float sr[9][256];
    __shared__ float red[256];
    int tid = threadIdx.x;
    int p = tid, py = p >> 4, px = p & 15;
    float ss = 0.f;
    #pragma unroll
    for (int ij = 0; ij < 9; ij++) {
        int di = ij / 3 - 1, dj = ij % 3 - 1;
        int y = py + di, x = px + dj;
        if ((unsigned)y < 16u && (unsigned)x < 16u) {
            int u = y * 16 + x;
            ss += g_R[u * 256 + u];
        }
    }
    float norm = fmaxf(sqrtf(ss), 1e-4f);
    #pragma unroll
    for (int ij = 0; ij < 9; ij++) {
        int di = ij / 3 - 1, dj = ij % 3 - 1;
        int y = qy + di, x = qx + dj;
        sr[ij][tid] = ((unsigned)y < 16u && (unsigned)x < 16u)
                    ? g_R[(y * 16 + x) * 256 + tid] : 0.f;
    }
    __syncthreads();
    float v = 0.f;
    #pragma unroll
    for (int ij = 0; ij < 9; ij++) {
        int di = ij / 3 - 1, dj = ij % 3 - 1;
        int y = py + di, x = px + dj;
        if ((unsigned)y < 16u && (unsigned)x < 16u) v += sr[ij][y * 16 + x];
    }
    v = v * 10.f / norm;
    red[p] = v; __syncthreads();
    for (int s = 128; s > 0; s >>= 1) { if (p < s) red[p] = fmaxf(red[p], red[p + s]); __syncthreads(); }
    float mx = red[0]; __syncthreads();
    float e = __expf(v - mx);
    red[p] = e; __syncthreads();
    for (int s = 128; s > 0; s >>= 1) { if (p < s) red[p] += red[p + s]; __syncthreads(); }
    float inv = 1.f / red[0];
    g_attnT[q * 256 + p] = e * inv;
}

// ---------------- 9) scatter deconv taps -> out_32 pixel-major ----------------
__global__ __launch_bounds__(512) void ral_out_kernel() {
    int pix = blockIdx.x;
    int ho = pix >> 5, wo = pix & 31;
    int c = threadIdx.x;
    float acc = 0.f;
    for (int ki = (ho + 1) & 1; ki < 4; ki += 2) {
        int qy = (ho + 1 - ki) >> 1;
        if ((unsigned)qy >= 16u) continue;
        for (int kj = (wo + 1) & 1; kj < 4; kj += 2) {
            int qx = (wo + 1 - kj) >> 1;
            if ((unsigned)qx >= 16u) continue;
            int q = qy * 16 + qx;
            acc += g_T[(size_t)q * 8192 + (ki * 4 + kj) * 512 + c];
        }
    }
    g_out32T[(size_t)pix * 512 + c] = acc * 0.25f;
}

// ------ union: gauss stage-1 (blocks 0..31, one per y, 512 thr covers all c)
//               + CSA (blocks 32..1055, pos = bx-32) ------
__global__ __launch_bounds__(512) void gauss1_csa_kernel() {
    __shared__ float sh[1024];      // gauss: gx table; csa: unused spare
    __shared__ float s_sum[16 * 9];
    __shared__ float s_a[9];
    int bx = blockIdx.x;
    int tid = threadIdx.x;
    if (bx < 32) {
        int y = bx;
        int c = tid;                // 0..511
        for (int e = tid; e < 1024; e += 512) {
            int i = e >> 5, xx = e & 31;
            float d = (float)(xx - i);
            sh[e] = __expf(-d * d * (1.f / 4.5f));
        }
        __syncthreads();
        float vals[32];
        #pragma unroll
        for (int xx = 0; xx < 32; xx++)
            vals[xx] = g_out32T[(size_t)(xx * 32 + y) * 512 + c];
        for (int i = 0; i < 32; i++) {
            float acc = 0.f;
            const float* gr = &sh[i * 32];
            #pragma unroll
            for (int xx = 0; xx < 32; xx++) acc += gr[xx] * vals[xx];
            g_T[(size_t)(i * 32 + y) * 512 + c] = acc;
        }
        return;
    }
    // ---- CSA ----
    int pos = bx - 32;
    int y = pos >> 5, x = pos & 31;
    int c = tid;
    float center = g_out32T[(size_t)pos * 512 + c];
    float sc = 1.f / (1.f + __expf(-center));
    float nb[9], pr[9];
    #pragma unroll
    for (int ij = 0; ij < 9; ij++) {
        int di = ij / 3 - 1, dj = ij % 3 - 1;
        int yy = y + di, xx = x + dj;
        bool ok = (unsigned)yy < 32u && (unsigned)xx < 32u;
        float v = ok ? g_out32T[(size_t)(yy * 32 + xx) * 512 + c] : 0.f;
        nb[ij] = v;
        float sn = ok ? 1.f / (1.f + __expf(-v)) : 0.f;
        pr[ij] = sc * sn;
    }
    #pragma unroll
    for (int ij = 0; ij < 9; ij++)
        #pragma unroll
        for (int o = 16; o > 0; o >>= 1) pr[ij] += __shfl_down_sync(0xFFFFFFFFu, pr[ij], o);
    int w = c >> 5, l = c & 31;
    if (l == 0) {
        #pragma unroll
        for (int ij = 0; ij < 9; ij++) s_sum[w * 9 + ij] = pr[ij];
    }
    __syncthreads();
    if (c < 9) {
        float t = 0.f;
        for (int w2 = 0; w2 < 16; w2++) t += s_sum[w2 * 9 + c];
        s_a[c] = t * (1.f / 512.f);
    }
    __syncthreads();
    if (c == 0) {
        float mx = s_a[0];
        for (int ij = 1; ij < 9; ij++) mx = fmaxf(mx, s_a[ij]);
        float sum = 0.f; float e[9];
        for (int ij = 0; ij < 9; ij++) { e[ij] = __expf(s_a[ij] - mx); sum += e[ij]; }
        float invs = 1.f / sum;
        for (int ij = 0; ij < 9; ij++) s_a[ij] = e[ij] * invs;
    }
    __syncthreads();
    float out = 0.f;
    #pragma unroll
    for (int ij = 0; ij < 9; ij++) out += s_a[ij] * nb[ij];
    g_z[512 * 1024 + (size_t)pos * 512 + c] = out;
}

// ------ gaussian stage 2 ------
__global__ __launch_bounds__(128) void gauss2_kernel() {
    int i = blockIdx.x;
    int cc = blockIdx.y;
    int c = cc * 128 + threadIdx.x;
    const float scale = 1.f / (2.f * 3.14159265358979323846f * 2.25f);
    __shared__ float gys[32 * 32];
    for (int e = threadIdx.x; e < 1024; e += 128) {
        int k = e >> 5, yy = e & 31;
        float d = (float)(yy - k);
        gys[e] = __expf(-d * d * (1.f / 4.5f));
    }
    __syncthreads();
    float vals[32];
    #pragma unroll
    for (int yy = 0; yy < 32; yy++)
        vals[yy] = g_T[(size_t)(i * 32 + yy) * 512 + c];
    for (int k = 0; k < 32; k++) {
        float acc = 0.f;
        const float* gr = &gys[k * 32];
        #pragma unroll
        for (int yy = 0; yy < 32; yy++) acc += gr[yy] * vals[yy];
        g_z[(size_t)(i * 32 + k) * 512 + c] = acc * scale;
    }
}

// ------------- instance norm + leaky relu; sums npart slices; optional concat copy ----
__global__ __launch_bounds__(256) void norm_leaky_kernel(
    const float* __restrict__ in, int npart, float* __restrict__ outA,
    const float* __restrict__ cpsrc, float* __restrict__ outB) {
    __shared__ float s_red[64];
    int c = blockIdx.x, tid = threadIdx.x;
    float v[4]; float s = 0.f, s2 = 0.f;
    #pragma unroll
    for (int q = 0; q < 4; q++) {
        int idx = c * 1024 + tid + q * 256;
        float acc = in[idx];
        for (int z = 1; z < npart; z++) acc += in[(size_t)z * 512 * 1024 + idx];
        v[q] = acc;
        s += acc; s2 += acc * acc;
    }
    blockReduce2(s, s2, s_red);
    float mu = s * (1.f / 1024.f);
    float inv = rsqrtf(s2 * (1.f / 1024.f) - mu * mu + 1e-5f);
    #pragma unroll
    for (int q = 0; q < 4; q++) {
        float f = (v[q] - mu) * inv;
        outA[c * 1024 + tid + q * 256] = f >= 0.f ? f : 0.2f * f;
    }
    if (cpsrc != nullptr) {
        #pragma unroll
        for (int q = 0; q < 4; q++)
            outB[c * 1024 + tid + q * 256] = cpsrc[c * 1024 + tid + q * 256];
    }
}

// ---------------- host ----------------
extern "C" void kernel_launch(void* const* d_in, const int* in_sizes, int n_in,
                              void* d_out, int out_size) {
    const float* x     = (const float*)d_in[0];
    const float* w_sk3 = (const float*)d_in[2];
    const float* b_sk3 = (const float*)d_in[3];
    const float* w_sk5 = (const float*)d_in[4];
    const float* b_sk5 = (const float*)d_in[5];
    const float* w_sk7 = (const float*)d_in[6];
    const float* b_sk7 = (const float*)d_in[7];
    const float* w_fc  = (const float*)d_in[8];
    const float* b_fc  = (const float*)d_in[9];
    const float* w_fc0 = (const float*)d_in[10];
    const float* b_fc0 = (const float*)d_in[11];
    const float* w_fc1 = (const float*)d_in[12];
    const float* b_fc1 = (const float*)d_in[13];
    const float* w_fc2 = (const float*)d_in[14];
    const float* b_fc2 = (const float*)d_in[15];
    const float* w_down = (const float*)d_in[16];
    const float* w_fuse = (const float*)d_in[17];

    float *fgsT, *S, *R, *attnT, *T, *z, *d1, *z2, *outres;
    cudaGetSymbolAddress((void**)&fgsT, g_fgsT);
    cudaGetSymbolAddress((void**)&S, g_S);
    cudaGetSymbolAddress((void**)&R, g_R);
    cudaGetSymbolAddress((void**)&attnT, g_attnT);
    cudaGetSymbolAddress((void**)&T, g_T);
    cudaGetSymbolAddress((void**)&z, g_z);
    cudaGetSymbolAddress((void**)&d1, g_d1);
    cudaGetSymbolAddress((void**)&z2, g_z2);
    cudaGetSymbolAddress((void**)&outres, g_outres);

    // SKConv all branches (R11 scalar, pipelined)
    sk_conv_all<<<dim3(512, 3), 128>>>(x, w_sk3, b_sk3, w_sk5, b_sk5, w_sk7, b_sk7);
    fz_kernel<<<32, 256>>>(w_fc, b_fc);
    combine_kernel<<<512, 256>>>(w_fc0, b_fc0, w_fc1, b_fc1, w_fc2, b_fc2);
    // RAL Gram matrix R = F F^T (fp32, 64x64 tiles, k-tile 16, split-K 8)
    gemm64_nt<<<dim3(4, 4, 8), 256>>>(fgsT, S, 256, 512, 8);
    reduceN_kernel<<<256, 256>>>(S, R, 256 * 256, 8);
    score_softmax_kernel<<<256, 256>>>();
    // deconv-as-GEMM (bf16x2): T' = attnT * gather(bg)^T
    gemm128_bf16<true, true><<<dim3(64, 2, 1), 256>>>(attnT, outres, T, 256, 8192, 256, 1);
    ral_out_kernel<<<1024, 512>>>();
    // gauss stage-1 + CSA in one launch (independent consumers of out32T)
    gauss1_csa_kernel<<<1056, 512>>>();
    gauss2_kernel<<<dim3(32, 4), 128>>>();
    // down 1x1 conv (bf16x2, split-K 4) + IN + leaky, concat out_res
    gemm128_bf16<false, false><<<dim3(8, 4, 4), 256>>>(w_down, z, d1, 512, 1024, 1024, 4);
    norm_leaky_kernel<<<512, 256>>>(d1, 4, z2, outres, z2 + 512 * 1024);
    // fuse 1x1 conv (bf16x2, split-K 4) + IN + leaky -> output
    gemm128_bf16<false, false><<<dim3(8, 4, 4), 256>>>(w_fuse, z2, d1, 512, 1024, 1024, 4);
    norm_leaky_kernel<<<512, 256>>>(d1, 4, (float*)d_out, nullptr, nullptr);
}

// round 15
// speedup vs baseline: 1.0507x; 1.0125x over previous
#include <cuda_runtime.h>
#include <cuda_bf16.h>
#include <mma.h>
#include <cstddef>

using namespace nvcuda;

// ---------------- scratch (static __device__, no allocs) ----------------
__device__ float g_feas[3 * 512 * 1024];
__device__ float g_bsum[3 * 512];
__device__ float g_fz[32];
__device__ float g_outres[512 * 1024];
__device__ float g_fgsT[256 * 512];       // fg_small, pixel-major [pos][c]
__device__ float g_R[256 * 256];          // R = F F^T (atomic-accumulated)
__device__ float g_attnT[256 * 256];      // attn transposed: [q][p]
__device__ float g_T[256 * 8192];         // T'[q][row]; reused for gaussian stage-1
__device__ float g_out32T[1024 * 512];    // post-RAL out_32, pixel-major
__device__ float g_z[1024 * 1024];        // concat(gus_out, out_csa)
__device__ float g_d1[4 * 512 * 1024];    // split-K partials of down/fuse
__device__ float g_z2[1024 * 1024];       // concat(leaky(norm(down)), out_res)

// ---------------- helpers ----------------
__device__ __forceinline__ void blockReduce2(float& s, float& s2, float* sm) {
    __syncthreads();
    int tid = threadIdx.x;
    #pragma unroll
    for (int o = 16; o > 0; o >>= 1) {
        s  += __shfl_down_sync(0xFFFFFFFFu, s, o);
        s2 += __shfl_down_sync(0xFFFFFFFFu, s2, o);
    }
    int w = tid >> 5, l = tid & 31;
    int nw = blockDim.x >> 5;
    if (l == 0) { sm[w] = s; sm[32 + w] = s2; }
    __syncthreads();
    if (tid < 32) {
        s  = (tid < nw) ? sm[tid] : 0.f;
        s2 = (tid < nw) ? sm[32 + tid] : 0.f;
        #pragma unroll
        for (int o = 16; o > 0; o >>= 1) {
            s  += __shfl_down_sync(0xFFFFFFFFu, s, o);
            s2 += __shfl_down_sync(0xFFFFFFFFu, s2, o);
        }
        if (tid == 0) { sm[0] = s; sm[32] = s2; }
    }
    __syncthreads();
    s = sm[0]; s2 = sm[32];
}

// ------- 1) SK grouped conv: 128 thr, 8 px/thread, pipelined ic tiles (R11 scalar) -------
template <int KS>
__device__ __forceinline__ void sk_conv_impl(
    const float* __restrict__ x, const float* __restrict__ w,
    const float* __restrict__ bias, int branch,
    float* s_ch, float* s_w, float* s_red) {
    constexpr int PAD = KS / 2;
    constexpr int W = 32 + 2 * PAD;
    int oc = blockIdx.x;
    int tid = threadIdx.x;
    int y = tid >> 2, xq = (tid & 3) * 8;
    const float* xin = x + (size_t)(oc >> 4) * 16 * 1024;
    const float* wo = w + (size_t)oc * 16 * KS * KS;
    for (int i = tid; i < 16 * KS * KS; i += 128) s_w[i] = wo[i];
    for (int i = tid; i < W * W; i += 128) s_ch[i] = 0.f;

    float pre[8];
    #pragma unroll
    for (int j = 0; j < 8; j++) pre[j] = xin[tid + j * 128];

    float acc[8] = {0.f, 0.f, 0.f, 0.f, 0.f, 0.f, 0.f, 0.f};
    for (int ic = 0; ic < 16; ic++) {
        __syncthreads();
        #pragma unroll
        for (int j = 0; j < 8; j++) {
            int i = tid + j * 128;
            int yy = i >> 5, xx = i & 31;
            s_ch[(yy + PAD) * W + xx + PAD] = pre[j];
        }
        __syncthreads();
        if (ic < 15) {
            #pragma unroll
            for (int j = 0; j < 8; j++) pre[j] = xin[(ic + 1) * 1024 + tid + j * 128];
        }
        const float* wi = &s_w[ic * KS * KS];
        #pragma unroll
        for (int ky = 0; ky < KS; ky++) {
            const float* rowp = &s_ch[(y + ky) * W + xq];
            float r[KS + 7];
            #pragma unroll
            for (int j = 0; j < KS + 7; j++) r[j] = rowp[j];
            #pragma unroll
            for (int kx = 0; kx < KS; kx++) {
                float wv = wi[ky * KS + kx];
                #pragma unroll
                for (int t = 0; t < 8; t++) acc[t] += r[kx + t] * wv;
            }
        }
    }
    float b = bias[oc];
    float s = 0.f, s2 = 0.f;
    #pragma unroll
    for (int t = 0; t < 8; t++) { acc[t] += b; s += acc[t]; s2 += acc[t] * acc[t]; }
    blockReduce2(s, s2, s_red);
    float mu = s * (1.f / 1024.f);
    float var = s2 * (1.f / 1024.f) - mu * mu;
    float inv = rsqrtf(var + 1e-5f);
    float rs = 0.f;
    float* fo = &g_feas[(size_t)branch * 512 * 1024 + (size_t)oc * 1024];
    float rv[8];
    #pragma unroll
    for (int t = 0; t < 8; t++) {
        float r = (acc[t] - mu) * inv;
        r = fmaxf(r, 0.f);
        rv[t] = r;
        rs += r;
    }
    *(float4*)(fo + y * 32 + xq)     = make_float4(rv[0], rv[1], rv[2], rv[3]);
    *(float4*)(fo + y * 32 + xq + 4) = make_float4(rv[4], rv[5], rv[6], rv[7]);
    float dummy = 0.f;
    blockReduce2(rs, dummy, s_red);
    if (tid == 0) g_bsum[branch * 512 + oc] = rs;
}

__global__ __launch_bounds__(128) void sk_conv_all(
    const float* __restrict__ x,
    const float* __restrict__ w3, const float* __restrict__ b3,
    const float* __restrict__ w5, const float* __restrict__ b5,
    const float* __restrict__ w7, const float* __restrict__ b7) {
    __shared__ float s_ch[38 * 38];
    __shared__ float s_w[16 * 49];
    __shared__ float s_red[64];
    int br = blockIdx.y;
    if (br == 0)      sk_conv_impl<3>(x, w3, b3, 0, s_ch, s_w, s_red);
    else if (br == 1) sk_conv_impl<5>(x, w5, b5, 1, s_ch, s_w, s_red);
    else              sk_conv_impl<7>(x, w7, b7, 2, s_ch, s_w, s_red);
}

// ---------------- 2) FC1 ----------------
__global__ __launch_bounds__(256) void fz_kernel(
    const float* __restrict__ w_fc, const float* __restrict__ b_fc) {
    __shared__ float s_red[64];
    int j = blockIdx.x, tid = threadIdx.x;
    float s = 0.f;
    for (int c = tid; c < 512; c += 256) {
        float fs = (g_bsum[c] + g_bsum[512 + c] + g_bsum[1024 + c]) * (1.f / 1024.f);
        s += fs * w_fc[j * 512 + c];
    }
    float dummy = 0.f;
    blockReduce2(s, dummy, s_red);
    if (tid == 0) g_fz[j] = s + b_fc[j];
}

// ------- 3) per-channel attention + combine -> out_res; avg pool -> fgsT; zero g_R ------
__global__ __launch_bounds__(256) void combine_kernel(
    const float* __restrict__ w0, const float* __restrict__ b0,
    const float* __restrict__ w1, const float* __restrict__ b1,
    const float* __restrict__ w2, const float* __restrict__ b2) {
    int c = blockIdx.x, tid = threadIdx.x;
    __shared__ float s_fz[32];
    __shared__ float s_a[3];
    __shared__ float s_o[1024];
    // zero g_R for atomic accumulation (65536 floats over 512 blocks)
    int gi = c * 256 + tid;
    if (gi < 65536) g_R[gi] = 0.f;
    if (tid < 32) s_fz[tid] = g_fz[tid];
    __syncthreads();
    int w = tid >> 5, l = tid & 31;
    if (w < 3) {
        const float* wt = (w == 0) ? w0 : (w == 1) ? w1 : w2;
        const float* bt = (w == 0) ? b0 : (w == 1) ? b1 : b2;
        float v = s_fz[l] * wt[c * 32 + l];
        #pragma unroll
        for (int o = 16; o > 0; o >>= 1) v += __shfl_down_sync(0xFFFFFFFFu, v, o);
        if (l == 0) s_a[w] = v + bt[c];
    }
    __syncthreads();
    float A0 = s_a[0], A1 = s_a[1], A2 = s_a[2];
    float mx = fmaxf(A0, fmaxf(A1, A2));
    float e0 = __expf(A0 - mx), e1 = __expf(A1 - mx), e2 = __expf(A2 - mx);
    float inv = 1.f / (e0 + e1 + e2);
    float a0 = e0 * inv, a1 = e1 * inv, a2 = e2 * inv;

    for (int i = tid; i < 1024; i += 256) {
        float v = a0 * g_feas[(size_t)c * 1024 + i]
                + a1 * g_feas[512 * 1024 + (size_t)c * 1024 + i]
                + a2 * g_feas[2 * 512 * 1024 + (size_t)c * 1024 + i];
        g_outres[c * 1024 + i] = v;
        s_o[i] = v;
    }
    __syncthreads();
    int py = tid >> 4, px = tid & 15;
    float p = 0.25f * (s_o[(2 * py) * 32 + 2 * px] + s_o[(2 * py) * 32 + 2 * px + 1] +
                       s_o[(2 * py + 1) * 32 + 2 * px] + s_o[(2 * py + 1) * 32 + 2 * px + 1]);
    g_fgsT[(size_t)tid * 512 + c] = p;
}

// ---- fp32 64x64-tile NT SGEMM for R = F F^T; atomic-accumulates into g_R ----
__global__ __launch_bounds__(256) void gemm64_nt(
    const float* __restrict__ A, float* __restrict__ C,
    int M, int K, int ksplit) {
    __shared__ float As[16][68];
    __shared__ float Bs[16][68];
    int tid = threadIdx.x;
    int bm = blockIdx.y * 64, bn = blockIdx.x * 64;
    int kchunk = K / ksplit, k0 = blockIdx.z * kchunk, kend = k0 + kchunk;
    int lr = tid >> 2, lc = (tid & 3) * 4;
    int tx = tid & 15, ty = tid >> 4;

    float4 pa, pb;
    auto loadAB = [&](int kk) {
        pa = *(const float4*)(A + (size_t)(bm + lr) * K + kk + lc);
        pb = *(const float4*)(A + (size_t)(bn + lr) * K + kk + lc);
    };
    auto storeTiles = [&]() {
        As[lc][lr] = pa.x; As[lc + 1][lr] = pa.y; As[lc + 2][lr] = pa.z; As[lc + 3][lr] = pa.w;
        Bs[lc][lr] = pb.x; Bs[lc + 1][lr] = pb.y; Bs[lc + 2][lr] = pb.z; Bs[lc + 3][lr] = pb.w;
    };

    float acc[4][4] = {};
    loadAB(k0);
    for (int kk = k0; kk < kend; kk += 16) {
        storeTiles();
        __syncthreads();
        if (kk + 16 < kend) loadAB(kk + 16);
        #pragma unroll
        for (int k = 0; k < 16; k++) {
            float4 a = *(const float4*)&As[k][ty * 4];
            float4 b = *(const float4*)&Bs[k][tx * 4];
            float ar[4] = {a.x, a.y, a.z, a.w};
            float br[4] = {b.x, b.y, b.z, b.w};
            #pragma unroll
            for (int i = 0; i < 4; i++)
                #pragma unroll
                for (int j = 0; j < 4; j++) acc[i][j] += ar[i] * br[j];
        }
        __syncthreads();
    }
    #pragma unroll
    for (int i = 0; i < 4; i++)
        #pragma unroll
        for (int j = 0; j < 4; j++)
            atomicAdd(&C[(size_t)(bm + ty * 4 + i) * M + bn + tx * 4 + j], acc[i][j]);
}

// ---- bf16x2-split WMMA 128x128-tile GEMM (3-mma Ootomo) ----
template <bool BT, bool GATHER>
__global__ __launch_bounds__(256) void gemm128_bf16(
    const float* __restrict__ A, const float* __restrict__ B, float* __restrict__ C,
    int M, int N, int K, int ksplit) {
    constexpr int LDA = 40;
    constexpr int LDBN = 136;
    __shared__ alignas(16) __nv_bfloat16 Ah[128 * LDA], Al[128 * LDA];
    __shared__ alignas(16) __nv_bfloat16 Bh[128 * LDA], Bl[128 * LDA];
    int tid = threadIdx.x;
    int bm = blockIdx.y * 128, bn = blockIdx.x * 128;
    int kchunk = K / ksplit, k0 = blockIdx.z * kchunk, kend = k0 + kchunk;
    C += (size_t)blockIdx.z * M * N;
    int lr = tid >> 2, lc = (tid & 3) * 4;
    int brow = tid >> 5, bcol = (tid & 31) * 4;

    float4 pa[2], pb[2];
    auto loadA = [&](int kk) {
        #pragma unroll
        for (int h = 0; h < 2; h++)
            pa[h] = *(const float4*)(A + (size_t)(bm + lr + h * 64) * K + kk + lc);
    };
    auto loadB = [&](int kk) {
        if (GATHER) {
            #pragma unroll
            for (int h = 0; h < 2; h++) {
                int n = bn + lr + h * 64;
                int combo = n >> 9, c = n & 511;
                int ki = combo >> 2, kj = combo & 3;
                float v[4];
                #pragma unroll
                for (int t = 0; t < 4; t++) {
                    int p = kk + lc + t;
                    int py = p >> 4, px = p & 15;
                    int r = 2 * py + ki - 1, col = 2 * px + kj - 1;
                    v[t] = ((unsigned)r < 32u && (unsigned)col < 32u)
                         ? B[c * 1024 + r * 32 + col] : 0.f;
                }
                pb[h] = make_float4(v[0], v[1], v[2], v[3]);
            }
        } else if (BT) {
            #pragma unroll
            for (int h = 0; h < 2; h++)
                pb[h] = *(const float4*)(B + (size_t)(bn + lr + h * 64) * K + kk + lc);
        } else {
            #pragma unroll
            for (int h = 0; h < 2; h++)
                pb[h] = *(const float4*)(B + (size_t)(kk + brow + h * 8) * N + bn + bcol);
        }
    };
    auto split2 = [](__nv_bfloat16* hp, __nv_bfloat16* lp, float v0, float v1) {
        __nv_bfloat16 h0 = __float2bfloat16(v0), h1 = __float2bfloat16(v1);
        *reinterpret_cast<__nv_bfloat162*>(hp) = __halves2bfloat162(h0, h1);
        __nv_bfloat16 l0 = __float2bfloat16(v0 - __bfloat162float(h0));
        __nv_bfloat16 l1 = __float2bfloat16(v1 - __bfloat162float(h1));
        *reinterpret_cast<__nv_bfloat162*>(lp) = __halves2bfloat162(l0, l1);
    };
    auto storeTiles = [&]() {
        #pragma unroll
        for (int h = 0; h < 2; h++) {
            int m = lr + h * 64;
            int idx = m * LDA + lc;
            split2(&Ah[idx], &Al[idx], pa[h].x, pa[h].y);
            split2(&Ah[idx + 2], &Al[idx + 2], pa[h].z, pa[h].w);
        }
        if (BT || GATHER) {
            #pragma unroll
            for (int h = 0; h < 2; h++) {
                int n = lr + h * 64;
                int idx = n * LDA + lc;
                split2(&Bh[idx], &Bl[idx], pb[h].x, pb[h].y);
                split2(&Bh[idx + 2], &Bl[idx + 2], pb[h].z, pb[h].w);
            }
        } else {
            #pragma unroll
            for (int h = 0; h < 2; h++) {
                int idx = (brow + h * 8) * LDBN + bcol;
                split2(&Bh[idx], &Bl[idx], pb[h].x, pb[h].y);
                split2(&Bh[idx + 2], &Bl[idx + 2], pb[h].z, pb[h].w);
            }
        }
    };

    int warp = tid >> 5;
    int wm = warp & 3, wn = warp >> 2;
    wmma::fragment<wmma::accumulator, 16, 16, 16, float> cf[2][4];
    #pragma unroll
    for (int i = 0; i < 2; i++)
        #pragma unroll
        for (int j = 0; j < 4; j++) wmma::fill_fragment(cf[i][j], 0.f);

    loadA(k0); loadB(k0);
    for (int kk = k0; kk < kend; kk += 16) {
        storeTiles();
        __syncthreads();
        if (kk + 16 < kend) { loadA(kk + 16); loadB(kk + 16); }
        wmma::fragment<wmma::matrix_a, 16, 16, 16, __nv_bfloat16, wmma::row_major> afh[2], afl[2];
        #pragma unroll
        for (int i = 0; i < 2; i++) {
            int m0 = wm * 32 + i * 16;
            wmma::load_matrix_sync(afh[i], &Ah[m0 * LDA], LDA);
            wmma::load_matrix_sync(afl[i], &Al[m0 * LDA], LDA);
        }
        if (BT || GATHER) {
            wmma::fragment<wmma::matrix_b, 16, 16, 16, __nv_bfloat16, wmma::col_major> bfh[4], bfl[4];
            #pragma unroll
            for (int j = 0; j < 4; j++) {
                int n0 = wn * 64 + j * 16;
                wmma::load_matrix_sync(bfh[j], &Bh[n0 * LDA], LDA);
                wmma::load_matrix_sync(bfl[j], &Bl[n0 * LDA], LDA);
            }
            #pragma unroll
            for (int i = 0; i < 2; i++)
                #pragma unroll
                for (int j = 0; j < 4; j++) {
                    wmma::mma_sync(cf[i][j], afh[i], bfh[j], cf[i][j]);
                    wmma::mma_sync(cf[i][j], afh[i], bfl[j], cf[i][j]);
                    wmma::mma_sync(cf[i][j], afl[i], bfh[j], cf[i][j]);
                }
        } else {
            wmma::fragment<wmma::matrix_b, 16, 16, 16, __nv_bfloat16, wmma::row_major> bfh[4], bfl[4];
            #pragma unroll
            for (int j = 0; j < 4; j++) {
                int n0 = wn * 64 + j * 16;
                wmma::load_matrix_sync(bfh[j], &Bh[n0], LDBN);
                wmma::load_matrix_sync(bfl[j], &Bl[n0], LDBN);
            }
            #pragma unroll
            for (int i = 0; i < 2; i++)
                #pragma unroll
                for (int j = 0; j < 4; j++) {
                    wmma::mma_sync(cf[i][j], afh[i], bfh[j], cf[i][j]);
                    wmma::mma_sync(cf[i][j], afh[i], bfl[j], cf[i][j]);
                    wmma::mma_sync(cf[i][j], afl[i], bfh[j], cf[i][j]);
                }
        }
        __syncthreads();
    }
    #pragma unroll
    for (int i = 0; i < 2; i++)
        #pragma unroll
        for (int j = 0; j < 4; j++) {
            int row = bm + wm * 32 + i * 16;
            int col = bn + wn * 64 + j * 16;
            wmma::store_matrix_sync(C + (size_t)row * N + col, cf[i][j], N, wmma::mem_row_major);
        }
}

// ------ 6) fused score reconstruction (9-tap sum of R) + softmax; pnorm inline ------
__global__ __launch_bounds__(256) void score_softmax_kernel() {
    int q = blockIdx.x;
    int qy = q >> 4, qx = q & 15;
    __shared__ float sr[9][256];
    __shared__ float red[256];
    int tid = threadIdx.x;
    int p = tid, py = p >> 4, px = p & 15;
    float ss = 0.f;
    #pragma unroll
    for (int ij = 0; ij < 9; ij++) {
        int di = ij / 3 - 1, dj = ij % 3 - 1;
        int y = py + di, x = px + dj;
        if ((unsigned)y < 16u && (unsigned)x < 16u) {
            int u = y * 16 + x;
            ss += g_R[u * 256 + u];
        }
    }
    float norm = fmaxf(sqrtf(ss), 1e-4f);
    #pragma unroll
    for (int ij = 0; ij < 9; ij++) {
        int di = ij / 3 - 1, dj = ij % 3 - 1;
        int y = qy + di, x = qx + dj;
        sr[ij][tid] = ((unsigned)y < 16u && (unsigned)x < 16u)
                    ? g_R[(y * 16 + x) * 256 + tid] : 0.f;
    }
    __syncthreads();
    float v = 0.f;
    #pragma unroll
    for (int ij = 0; ij < 9; ij++) {
        int di = ij / 3 - 1, dj = ij % 3 - 1;
        int y = py + di, x = px + dj;
        if ((unsigned)y < 16u && (unsigned)x < 16u) v += sr[ij][y * 16 + x];
    }
    v = v * 10.f / norm;
    red[p] = v; __syncthreads();
    for (int s = 128; s > 0; s >>= 1) { if (p < s) red[p] = fmaxf(red[p], red[p + s]); __syncthreads(); }
    float mx = red[0]; __syncthreads();
    float e = __expf(v - mx);
    red[p] = e; __syncthreads();
    for (int s = 128; s > 0; s >>= 1) { if (p < s) red[p] += red[p + s]; __syncthreads(); }
    float inv = 1.f / red[0];
    g_attnT[q * 256 + p] = e * inv;
}

// ---------------- 9) scatter deconv taps -> out_32 pixel-major ----------------
__global__ __launch_bounds__(512) void ral_out_kernel() {
    int pix = blockIdx.x;
    int ho = pix >> 5, wo = pix & 31;
    int c = threadIdx.x;
    float acc = 0.f;
    for (int ki = (ho + 1) & 1; ki < 4; ki += 2) {
        int qy = (ho + 1 - ki) >> 1;
        if ((unsigned)qy >= 16u) continue;
        for (int kj = (wo + 1) & 1; kj < 4; kj += 2) {
            int qx = (wo + 1 - kj) >> 1;
            if ((unsigned)qx >= 16u) continue;
            int q = qy * 16 + qx;
            acc += g_T[(size_t)q * 8192 + (ki * 4 + kj) * 512 + c];
        }
    }
    g_out32T[(size_t)pix * 512 + c] = acc * 0.25f;
}

// ------ 10a) separable gaussian stage 1 (R11 version) ------
__global__ __launch_bounds__(128) void gauss1_kernel() {
    int y = blockIdx.x;
    int cc = blockIdx.y;
    int c = cc * 128 + threadIdx.x;
    __shared__ float gxs[32 * 32];
    for (int e = threadIdx.x; e < 1024; e += 128) {
        int i = e >> 5, xx = e & 31;
        float d = (float)(xx - i);
        gxs[e] = __expf(-d * d * (1.f / 4.5f));
    }
    __syncthreads();
    float vals[32];
    #pragma unroll
    for (int xx = 0; xx < 32; xx++)
        vals[xx] = g_out32T[(size_t)(xx * 32 + y) * 512 + c];
    for (int i = 0; i < 32; i++) {
        float acc = 0.f;
        const float* gr = &gxs[i * 32];
        #pragma unroll
        for (int xx = 0; xx < 32; xx++) acc += gr[xx] * vals[xx];
        g_T[(size_t)(i * 32 + y) * 512 + c] = acc;
    }
}

// ------ 10b) stage 2 ------
__global__ __launch_bounds__(128) void gauss2_kernel() {
    int i = blockIdx.x;
    int cc = blockIdx.y;
    int c = cc * 128 + threadIdx.x;
    const float scale = 1.f / (2.f * 3.14159265358979323846f * 2.25f);
    __shared__ float gys[32 * 32];
    for (int e = threadIdx.x; e < 1024; e += 128) {
        int k = e >> 5, yy = e & 31;
        float d = (float)(yy - k);
        gys[e] = __expf(-d * d * (1.f / 4.5f));
    }
    __syncthreads();
    float vals[32];
    #pragma unroll
    for (int yy = 0; yy < 32; yy++)
        vals[yy] = g_T[(size_t)(i * 32 + yy) * 512 + c];
    for (int k = 0; k < 32; k++) {
        float acc = 0.f;
        const float* gr = &gys[k * 32];
        #pragma unroll
        for (int yy = 0; yy < 32; yy++) acc += gr[yy] * vals[yy];
        g_z[(size_t)(i * 32 + k) * 512 + c] = acc * scale;
    }
}

// ---------------- 11) CSA (R11 version: inline sigmoids) ----------------
__global__ __launch_bounds__(512) void csa_kernel() {
    int pos = blockIdx.x;
    int y = pos >> 5, x = pos & 31;
    int c = threadIdx.x;
    __shared__ float s_sum[16 * 9];
    __shared__ float s_a[9];
    float center = g_out32T[(size_t)pos * 512 + c];
    float sc = 1.f / (1.f + __expf(-center));
    float nb[9], pr[9];
    #pragma unroll
    for (int ij = 0; ij < 9; ij++) {
        int di = ij / 3 - 1, dj = ij % 3 - 1;
        int yy = y + di, xx = x + dj;
        bool ok = (unsigned)yy < 32u && (unsigned)xx < 32u;
        float v = ok ? g_out32T[(size_t)(yy * 32 + xx) * 512 + c] : 0.f;
        nb[ij] = v;
        float sn = ok ? 1.f / (1.f + __expf(-v)) : 0.f;
        pr[ij] = sc * sn;
    }
    #pragma unroll
    for (int ij = 0; ij < 9; ij++)
        #pragma unroll
        for (int o = 16; o > 0; o >>= 1) pr[ij] += __shfl_down_sync(0xFFFFFFFFu, pr[ij], o);
    int w = c >> 5, l = c & 31;
    if (l == 0) {
        #pragma unroll
        for (int ij = 0; ij < 9; ij++) s_sum[w * 9 + ij] = pr[ij];
    }
    __syncthreads();
    if (c < 9) {
        float t = 0.f;
        for (int w2 = 0; w2 < 16; w2++) t += s_sum[w2 * 9 + c];
        s_a[c] = t * (1.f / 512.f);
    }
    __syncthreads();
    if (c == 0) {
        float mx = s_a[0];
        for (int ij = 1; ij < 9; ij++) mx = fmaxf(mx, s_a[ij]);
        float sum = 0.f; float e[9];
        for (int ij = 0; ij < 9; ij++) { e[ij] = __expf(s_a[ij] - mx); sum += e[ij]; }
        float invs = 1.f / sum;
        for (int ij = 0; ij < 9; ij++) s_a[ij] = e[ij] * invs;
    }
    __syncthreads();
    float out = 0.f;
    #pragma unroll
    for (int ij = 0; ij < 9; ij++) out += s_a[ij] * nb[ij];
    g_z[512 * 1024 + (size_t)pos * 512 + c] = out;
}

// ------------- instance norm + leaky relu; sums npart slices; optional concat copy ----
__global__ __launch_bounds__(256) void norm_leaky_kernel(
    const float* __restrict__ in, int npart, float* __restrict__ outA,
    const float* __restrict__ cpsrc, float* __restrict__ outB) {
    __shared__ float s_red[64];
    int c = blockIdx.x, tid = threadIdx.x;
    float v[4]; float s = 0.f, s2 = 0.f;
    #pragma unroll
    for (int q = 0; q < 4; q++) {
        int idx = c * 1024 + tid + q * 256;
        float acc = in[idx];
        for (int z = 1; z < npart; z++) acc += in[(size_t)z * 512 * 1024 + idx];
        v[q] = acc;
        s += acc; s2 += acc * acc;
    }
    blockReduce2(s, s2, s_red);
    float mu = s * (1.f / 1024.f);
    float inv = rsqrtf(s2 * (1.f / 1024.f) - mu * mu + 1e-5f);
    #pragma unroll
    for (int q = 0; q < 4; q++) {
        float f = (v[q] - mu) * inv;
        outA[c * 1024 + tid + q * 256] = f >= 0.f ? f : 0.2f * f;
    }
    if (cpsrc != nullptr) {
        #pragma unroll
        for (int q = 0; q < 4; q++)
            outB[c * 1024 + tid + q * 256] = cpsrc[c * 1024 + tid + q * 256];
    }
}

// ---------------- host ----------------
extern "C" void kernel_launch(void* const* d_in, const int* in_sizes, int n_in,
                              void* d_out, int out_size) {
    const float* x     = (const float*)d_in[0];
    const float* w_sk3 = (const float*)d_in[2];
    const float* b_sk3 = (const float*)d_in[3];
    const float* w_sk5 = (const float*)d_in[4];
    const float* b_sk5 = (const float*)d_in[5];
    const float* w_sk7 = (const float*)d_in[6];
    const float* b_sk7 = (const float*)d_in[7];
    const float* w_fc  = (const float*)d_in[8];
    const float* b_fc  = (const float*)d_in[9];
    const float* w_fc0 = (const float*)d_in[10];
    const float* b_fc0 = (const float*)d_in[11];
    const float* w_fc1 = (const float*)d_in[12];
    const float* b_fc1 = (const float*)d_in[13];
    const float* w_fc2 = (const float*)d_in[14];
    const float* b_fc2 = (const float*)d_in[15];
    const float* w_down = (const float*)d_in[16];
    const float* w_fuse = (const float*)d_in[17];

    float *fgsT, *R, *attnT, *T, *z, *d1, *z2, *outres;
    cudaGetSymbolAddress((void**)&fgsT, g_fgsT);
    cudaGetSymbolAddress((void**)&R, g_R);
    cudaGetSymbolAddress((void**)&attnT, g_attnT);
    cudaGetSymbolAddress((void**)&T, g_T);
    cudaGetSymbolAddress((void**)&z, g_z);
    cudaGetSymbolAddress((void**)&d1, g_d1);
    cudaGetSymbolAddress((void**)&z2, g_z2);
    cudaGetSymbolAddress((void**)&outres, g_outres);

    // SKConv all branches (R11 scalar, pipelined)
    sk_conv_all<<<dim3(512, 3), 128>>>(x, w_sk3, b_sk3, w_sk5, b_sk5, w_sk7, b_sk7);
    fz_kernel<<<32, 256>>>(w_fc, b_fc);
    combine_kernel<<<512, 256>>>(w_fc0, b_fc0, w_fc1, b_fc1, w_fc2, b_fc2);   // also zeroes g_R
    // RAL Gram matrix R = F F^T (fp32, split-K 8, atomic accumulate into g_R)
    gemm64_nt<<<dim3(4, 4, 8), 256>>>(fgsT, R, 256, 512, 8);
    score_softmax_kernel<<<256, 256>>>();
    // deconv-as-GEMM (bf16x2): T' = attnT * gather(bg)^T
    gemm128_bf16<true, true><<<dim3(64, 2, 1), 256>>>(attnT, outres, T, 256, 8192, 256, 1);
    ral_out_kernel<<<1024, 512>>>();
    // separable gaussian -> first half of z
    gauss1_kernel<<<dim3(32, 4), 128>>>();
    gauss2_kernel<<<dim3(32, 4), 128>>>();
    // CSA -> second half of z
    csa_kernel<<<1024, 512>>>();
    // down 1x1 conv (bf16x2, split-K 4) + IN + leaky, concat out_res
    gemm128_bf16<false, false><<<dim3(8, 4, 4), 256>>>(w_down, z, d1, 512, 1024, 1024, 4);
    norm_leaky_kernel<<<512, 256>>>(d1, 4, z2, outres, z2 + 512 * 1024);
    // fuse 1x1 conv (bf16x2, split-K 4) + IN + leaky -> output
    gemm128_bf16<false, false><<<dim3(8, 4, 4), 256>>>(w_fuse, z2, d1, 512, 1024, 1024, 4);
    norm_leaky_kernel<<<512, 256>>>(d1, 4, (float*)d_out, nullptr, nullptr);
}

// round 16
// speedup vs baseline: 1.0752x; 1.0233x over previous
#include <cuda_runtime.h>
#include <cuda_bf16.h>
#include <mma.h>
#include <cstddef>

using namespace nvcuda;

// ---------------- scratch (static __device__, no allocs) ----------------
__device__ float g_feas[3 * 512 * 1024];
__device__ float g_bsum[3 * 512];
__device__ float g_fz[32];
__device__ float g_outres[512 * 1024];
__device__ float g_fgsT[256 * 512];       // fg_small, pixel-major [pos][c]
__device__ float g_S[8 * 256 * 256];      // split-K partials of R = F F^T
__device__ float g_R[256 * 256];          // reduced R
__device__ float g_attnT[256 * 256];      // attn transposed: [q][p]
__device__ float g_T[256 * 8192];         // T'[q][row]; reused for gaussian stage-1
__device__ float g_out32T[1024 * 512];    // post-RAL out_32, pixel-major
__device__ float g_z[1024 * 1024];        // concat(gus_out, out_csa)
__device__ float g_d1[4 * 512 * 1024];    // split-K partials of down/fuse
__device__ float g_z2[1024 * 1024];       // concat(leaky(norm(down)), out_res)

// ---------------- helpers ----------------
__device__ __forceinline__ void blockReduce2(float& s, float& s2, float* sm) {
    __syncthreads();
    int tid = threadIdx.x;
    #pragma unroll
    for (int o = 16; o > 0; o >>= 1) {
        s  += __shfl_down_sync(0xFFFFFFFFu, s, o);
        s2 += __shfl_down_sync(0xFFFFFFFFu, s2, o);
    }
    int w = tid >> 5, l = tid & 31;
    int nw = blockDim.x >> 5;
    if (l == 0) { sm[w] = s; sm[32 + w] = s2; }
    __syncthreads();
    if (tid < 32) {
        s  = (tid < nw) ? sm[tid] : 0.f;
        s2 = (tid < nw) ? sm[32 + tid] : 0.f;
        #pragma unroll
        for (int o = 16; o > 0; o >>= 1) {
            s  += __shfl_down_sync(0xFFFFFFFFu, s, o);
            s2 += __shfl_down_sync(0xFFFFFFFFu, s2, o);
        }
        if (tid == 0) { sm[0] = s; sm[32] = s2; }
    }
    __syncthreads();
    s = sm[0]; s2 = sm[32];
}

// ------- 1) SK grouped conv: 128 thr, 8 px/thread, 2 oc/block, pipelined ic tiles -------
template <int KS>
__device__ __forceinline__ void sk_conv_impl(
    const float* __restrict__ x, const float* __restrict__ w,
    const float* __restrict__ bias, int branch,
    float* s_ch, float* s_w, float* s_red) {
    constexpr int PAD = KS / 2;
    constexpr int W = 32 + 2 * PAD;
    int oc0 = blockIdx.x * 2;            // two output channels of the same group
    int tid = threadIdx.x;
    int y = tid >> 2, xq = (tid & 3) * 8;
    const float* xin = x + (size_t)(oc0 >> 4) * 16 * 1024;
    const float* wo = w + (size_t)oc0 * 16 * KS * KS;
    for (int i = tid; i < 2 * 16 * KS * KS; i += 128) s_w[i] = wo[i];
    for (int i = tid; i < W * W; i += 128) s_ch[i] = 0.f;

    float pre[8];
    #pragma unroll
    for (int j = 0; j < 8; j++) pre[j] = xin[tid + j * 128];

    float acc[2][8] = {};
    for (int ic = 0; ic < 16; ic++) {
        __syncthreads();
        #pragma unroll
        for (int j = 0; j < 8; j++) {
            int i = tid + j * 128;
            int yy = i >> 5, xx = i & 31;
            s_ch[(yy + PAD) * W + xx + PAD] = pre[j];
        }
        __syncthreads();
        if (ic < 15) {
            #pragma unroll
            for (int j = 0; j < 8; j++) pre[j] = xin[(ic + 1) * 1024 + tid + j * 128];
        }
        const float* wi0 = &s_w[ic * KS * KS];
        const float* wi1 = &s_w[16 * KS * KS + ic * KS * KS];
        #pragma unroll
        for (int ky = 0; ky < KS; ky++) {
            const float* rowp = &s_ch[(y + ky) * W + xq];
            float r[KS + 7];
            #pragma unroll
            for (int j = 0; j < KS + 7; j++) r[j] = rowp[j];
            #pragma unroll
            for (int kx = 0; kx < KS; kx++) {
                float w0 = wi0[ky * KS + kx];
                float w1 = wi1[ky * KS + kx];
                #pragma unroll
                for (int t = 0; t < 8; t++) {
                    acc[0][t] += r[kx + t] * w0;
                    acc[1][t] += r[kx + t] * w1;
                }
            }
        }
    }
    #pragma unroll
    for (int o = 0; o < 2; o++) {
        int oc = oc0 + o;
        float b = bias[oc];
        float s = 0.f, s2 = 0.f;
        #pragma unroll
        for (int t = 0; t < 8; t++) {
            acc[o][t] += b;
            s += acc[o][t]; s2 += acc[o][t] * acc[o][t];
        }
        blockReduce2(s, s2, s_red);
        float mu = s * (1.f / 1024.f);
        float var = s2 * (1.f / 1024.f) - mu * mu;
        float inv = rsqrtf(var + 1e-5f);
        float rs = 0.f;
        float* fo = &g_feas[(size_t)branch * 512 * 1024 + (size_t)oc * 1024];
        float rv[8];
        #pragma unroll
        for (int t = 0; t < 8; t++) {
            float rr = (acc[o][t] - mu) * inv;
            rr = fmaxf(rr, 0.f);
            rv[t] = rr;
            rs += rr;
        }
        *(float4*)(fo + y * 32 + xq)     = make_float4(rv[0], rv[1], rv[2], rv[3]);
        *(float4*)(fo + y * 32 + xq + 4) = make_float4(rv[4], rv[5], rv[6], rv[7]);
        float dummy = 0.f;
        blockReduce2(rs, dummy, s_red);
        if (tid == 0) g_bsum[branch * 512 + oc] = rs;
    }
}

__global__ __launch_bounds__(128) void sk_conv_all(
    const float* __restrict__ x,
    const float* __restrict__ w3, const float* __restrict__ b3,
    const float* __restrict__ w5, const float* __restrict__ b5,
    const float* __restrict__ w7, const float* __restrict__ b7) {
    __shared__ float s_ch[38 * 38];
    __shared__ float s_w[2 * 16 * 49];
    __shared__ float s_red[64];
    int br = blockIdx.y;
    if (br == 0)      sk_conv_impl<3>(x, w3, b3, 0, s_ch, s_w, s_red);
    else if (br == 1) sk_conv_impl<5>(x, w5, b5, 1, s_ch, s_w, s_red);
    else              sk_conv_impl<7>(x, w7, b7, 2, s_ch, s_w, s_red);
}

// ---------------- 2) FC1 ----------------
__global__ __launch_bounds__(256) void fz_kernel(
    const float* __restrict__ w_fc, const float* __restrict__ b_fc) {
    __shared__ float s_red[64];
    int j = blockIdx.x, tid = threadIdx.x;
    float s = 0.f;
    for (int c = tid; c < 512; c += 256) {
        float fs = (g_bsum[c] + g_bsum[512 + c] + g_bsum[1024 + c]) * (1.f / 1024.f);
        s += fs * w_fc[j * 512 + c];
    }
    float dummy = 0.f;
    blockReduce2(s, dummy, s_red);
    if (tid == 0) g_fz[j] = s + b_fc[j];
}

// ------- 3) per-channel branch attention + combine -> out_res; avg pool -> fgsT ------
__global__ __launch_bounds__(256) void combine_kernel(
    const float* __restrict__ w0, const float* __restrict__ b0,
    const float* __restrict__ w1, const float* __restrict__ b1,
    const float* __restrict__ w2, const float* __restrict__ b2) {
    int c = blockIdx.x, tid = threadIdx.x;
    __shared__ float s_fz[32];
    __shared__ float s_a[3];
    __shared__ float s_o[1024];
    if (tid < 32) s_fz[tid] = g_fz[tid];
    __syncthreads();
    int w = tid >> 5, l = tid & 31;
    if (w < 3) {
        const float* wt = (w == 0) ? w0 : (w == 1) ? w1 : w2;
        const float* bt = (w == 0) ? b0 : (w == 1) ? b1 : b2;
        float v = s_fz[l] * wt[c * 32 + l];
        #pragma unroll
        for (int o = 16; o > 0; o >>= 1) v += __shfl_down_sync(0xFFFFFFFFu, v, o);
        if (l == 0) s_a[w] = v + bt[c];
    }
    __syncthreads();
    float A0 = s_a[0], A1 = s_a[1], A2 = s_a[2];
    float mx = fmaxf(A0, fmaxf(A1, A2));
    float e0 = __expf(A0 - mx), e1 = __expf(A1 - mx), e2 = __expf(A2 - mx);
    float inv = 1.f / (e0 + e1 + e2);
    float a0 = e0 * inv, a1 = e1 * inv, a2 = e2 * inv;

    for (int i = tid; i < 1024; i += 256) {
        float v = a0 * g_feas[(size_t)c * 1024 + i]
                + a1 * g_feas[512 * 1024 + (size_t)c * 1024 + i]
                + a2 * g_feas[2 * 512 * 1024 + (size_t)c * 1024 + i];
        g_outres[c * 1024 + i] = v;
        s_o[i] = v;
    }
    __syncthreads();
    int py = tid >> 4, px = tid & 15;
    float p = 0.25f * (s_o[(2 * py) * 32 + 2 * px] + s_o[(2 * py) * 32 + 2 * px + 1] +
                       s_o[(2 * py + 1) * 32 + 2 * px] + s_o[(2 * py + 1) * 32 + 2 * px + 1]);
    g_fgsT[(size_t)tid * 512 + c] = p;
}

// ---- fp32 64x64-tile NT SGEMM for R = F F^T (k-tile 16, split-K) ----
__global__ __launch_bounds__(256) void gemm64_nt(
    const float* __restrict__ A, float* __restrict__ C,
    int M, int K, int ksplit) {
    __shared__ float As[16][68];
    __shared__ float Bs[16][68];
    int tid = threadIdx.x;
    int bm = blockIdx.y * 64, bn = blockIdx.x * 64;
    int kchunk = K / ksplit, k0 = blockIdx.z * kchunk, kend = k0 + kchunk;
    C += (size_t)blockIdx.z * M * M;
    int lr = tid >> 2, lc = (tid & 3) * 4;
    int tx = tid & 15, ty = tid >> 4;

    float4 pa, pb;
    auto loadAB = [&](int kk) {
        pa = *(const float4*)(A + (size_t)(bm + lr) * K + kk + lc);
        pb = *(const float4*)(A + (size_t)(bn + lr) * K + kk + lc);
    };
    auto storeTiles = [&]() {
        As[lc][lr] = pa.x; As[lc + 1][lr] = pa.y; As[lc + 2][lr] = pa.z; As[lc + 3][lr] = pa.w;
        Bs[lc][lr] = pb.x; Bs[lc + 1][lr] = pb.y; Bs[lc + 2][lr] = pb.z; Bs[lc + 3][lr] = pb.w;
    };

    float acc[4][4] = {};
    loadAB(k0);
    for (int kk = k0; kk < kend; kk += 16) {
        storeTiles();
        __syncthreads();
        if (kk + 16 < kend) loadAB(kk + 16);
        #pragma unroll
        for (int k = 0; k < 16; k++) {
            float4 a = *(const float4*)&As[k][ty * 4];
            float4 b = *(const float4*)&Bs[k][tx * 4];
            float ar[4] = {a.x, a.y, a.z, a.w};
            float br[4] = {b.x, b.y, b.z, b.w};
            #pragma unroll
            for (int i = 0; i < 4; i++)
                #pragma unroll
                for (int j = 0; j < 4; j++) acc[i][j] += ar[i] * br[j];
        }
        __syncthreads();
    }
    #pragma unroll
    for (int i = 0; i < 4; i++)
        *(float4*)(C + (size_t)(bm + ty * 4 + i) * M + bn + tx * 4) =
            make_float4(acc[i][0], acc[i][1], acc[i][2], acc[i][3]);
}

// ---- bf16x2-split WMMA 128x128-tile GEMM (3-mma Ootomo) ----
template <bool BT, bool GATHER>
__global__ __launch_bounds__(256) void gemm128_bf16(
    const float* __restrict__ A, const float* __restrict__ B, float* __restrict__ C,
    int M, int N, int K, int ksplit) {
    constexpr int LDA = 40;
    constexpr int LDBN = 136;
    __shared__ alignas(16) __nv_bfloat16 Ah[128 * LDA], Al[128 * LDA];
    __shared__ alignas(16) __nv_bfloat16 Bh[128 * LDA], Bl[128 * LDA];
    int tid = threadIdx.x;
    int bm = blockIdx.y * 128, bn = blockIdx.x * 128;
    int kchunk = K / ksplit, k0 = blockIdx.z * kchunk, kend = k0 + kchunk;
    C += (size_t)blockIdx.z * M * N;
    int lr = tid >> 2, lc = (tid & 3) * 4;
    int brow = tid >> 5, bcol = (tid & 31) * 4;

    float4 pa[2], pb[2];
    auto loadA = [&](int kk) {
        #pragma unroll
        for (int h = 0; h < 2; h++)
            pa[h] = *(const float4*)(A + (size_t)(bm + lr + h * 64) * K + kk + lc);
    };
    auto loadB = [&](int kk) {
        if (GATHER) {
            #pragma unroll
            for (int h = 0; h < 2; h++) {
                int n = bn + lr + h * 64;
                int combo = n >> 9, c = n & 511;
                int ki = combo >> 2, kj = combo & 3;
                float v[4];
                #pragma unroll
                for (int t = 0; t < 4; t++) {
                    int p = kk + lc + t;
                    int py = p >> 4, px = p & 15;
                    int r = 2 * py + ki - 1, col = 2 * px + kj - 1;
                    v[t] = ((unsigned)r < 32u && (unsigned)col < 32u)
                         ? B[c * 1024 + r * 32 + col] : 0.f;
                }
                pb[h] = make_float4(v[0], v[1], v[2], v[3]);
            }
        } else if (BT) {
            #pragma unroll
            for (int h = 0; h < 2; h++)
                pb[h] = *(const float4*)(B + (size_t)(bn + lr + h * 64) * K + kk + lc);
        } else {
            #pragma unroll
            for (int h = 0; h < 2; h++)
                pb[h] = *(const float4*)(B + (size_t)(kk + brow + h * 8) * N + bn + bcol);
        }
    };
    auto split2 = [](__nv_bfloat16* hp, __nv_bfloat16* lp, float v0, float v1) {
        __nv_bfloat16 h0 = __float2bfloat16(v0), h1 = __float2bfloat16(v1);
        *reinterpret_cast<__nv_bfloat162*>(hp) = __halves2bfloat162(h0, h1);
        __nv_bfloat16 l0 = __float2bfloat16(v0 - __bfloat162float(h0));
        __nv_bfloat16 l1 = __float2bfloat16(v1 - __bfloat162float(h1));
        *reinterpret_cast<__nv_bfloat162*>(lp) = __halves2bfloat162(l0, l1);
    };
    auto storeTiles = [&]() {
        #pragma unroll
        for (int h = 0; h < 2; h++) {
            int m = lr + h * 64;
            int idx = m * LDA + lc;
            split2(&Ah[idx], &Al[idx], pa[h].x, pa[h].y);
            split2(&Ah[idx + 2], &Al[idx + 2], pa[h].z, pa[h].w);
        }
        if (BT || GATHER) {
            #pragma unroll
            for (int h = 0; h < 2; h++) {
                int n = lr + h * 64;
                int idx = n * LDA + lc;
                split2(&Bh[idx], &Bl[idx], pb[h].x, pb[h].y);
                split2(&Bh[idx + 2], &Bl[idx + 2], pb[h].z, pb[h].w);
            }
        } else {
            #pragma unroll
            for (int h = 0; h < 2; h++) {
                int idx = (brow + h * 8) * LDBN + bcol;
                split2(&Bh[idx], &Bl[idx], pb[h].x, pb[h].y);
                split2(&Bh[idx + 2], &Bl[idx + 2], pb[h].z, pb[h].w);
            }
        }
    };

    int warp = tid >> 5;
    int wm = warp & 3, wn = warp >> 2;
    wmma::fragment<wmma::accumulator, 16, 16, 16, float> cf[2][4];
    #pragma unroll
    for (int i = 0; i < 2; i++)
        #pragma unroll
        for (int j = 0; j < 4; j++) wmma::fill_fragment(cf[i][j], 0.f);

    loadA(k0); loadB(k0);
    for (int kk = k0; kk < kend; kk += 16) {
        storeTiles();
        __syncthreads();
        if (kk + 16 < kend) { loadA(kk + 16); loadB(kk + 16); }
        wmma::fragment<wmma::matrix_a, 16, 16, 16, __nv_bfloat16, wmma::row_major> afh[2], afl[2];
        #pragma unroll
        for (int i = 0; i < 2; i++) {
            int m0 = wm * 32 + i * 16;
            wmma::load_matrix_sync(afh[i], &Ah[m0 * LDA], LDA);
            wmma::load_matrix_sync(afl[i], &Al[m0 * LDA], LDA);
        }
        if (BT || GATHER) {
            wmma::fragment<wmma::matrix_b, 16, 16, 16, __nv_bfloat16, wmma::col_major> bfh[4], bfl[4];
            #pragma unroll
            for (int j = 0; j < 4; j++) {
                int n0 = wn * 64 + j * 16;
                wmma::load_matrix_sync(bfh[j], &Bh[n0 * LDA], LDA);
                wmma::load_matrix_sync(bfl[j], &Bl[n0 * LDA], LDA);
            }
            #pragma unroll
            for (int i = 0; i < 2; i++)
                #pragma unroll
                for (int j = 0; j < 4; j++) {
                    wmma::mma_sync(cf[i][j], afh[i], bfh[j], cf[i][j]);
                    wmma::mma_sync(cf[i][j], afh[i], bfl[j], cf[i][j]);
                    wmma::mma_sync(cf[i][j], afl[i], bfh[j], cf[i][j]);
                }
        } else {
            wmma::fragment<wmma::matrix_b, 16, 16, 16, __nv_bfloat16, wmma::row_major> bfh[4], bfl[4];
            #pragma unroll
            for (int j = 0; j < 4; j++) {
                int n0 = wn * 64 + j * 16;
                wmma::load_matrix_sync(bfh[j], &Bh[n0], LDBN);
                wmma::load_matrix_sync(bfl[j], &Bl[n0], LDBN);
            }
            #pragma unroll
            for (int i = 0; i < 2; i++)
                #pragma unroll
                for (int j = 0; j < 4; j++) {
                    wmma::mma_sync(cf[i][j], afh[i], bfh[j], cf[i][j]);
                    wmma::mma_sync(cf[i][j], afh[i], bfl[j], cf[i][j]);
                    wmma::mma_sync(cf[i][j], afl[i], bfh[j], cf[i][j]);
                }
        }
        __syncthreads();
    }
    #pragma unroll
    for (int i = 0; i < 2; i++)
        #pragma unroll
        for (int j = 0; j < 4; j++) {
            int row = bm + wm * 32 + i * 16;
            int col = bn + wn * 64 + j * 16;
            wmma::store_matrix_sync(C + (size_t)row * N + col, cf[i][j], N, wmma::mem_row_major);
        }
}

// ---------------- reduce npart split-K slices ----------------
__global__ __launch_bounds__(256) void reduceN_kernel(const float* __restrict__ in,
                                                      float* __restrict__ out,
                                                      int n, int npart) {
    int i = blockIdx.x * 256 + threadIdx.x;
    float s = in[i];
    for (int z = 1; z < npart; z++) s += in[(size_t)z * n + i];
    out[i] = s;
}

// ------ 6) fused score reconstruction (9-tap sum of R) + softmax; pnorm inline ------
__global__ __launch_bounds__(256) void score_softmax_kernel() {
    int q = blockIdx.x;
    int qy = q >> 4, qx = q & 15;
    __shared__ float sr[9][256];
    __shared__ float red[256];
    int tid = threadIdx.x;
    int p = tid, py = p >> 4, px = p & 15;
    float ss = 0.f;
    #pragma unroll
    for (int ij = 0; ij < 9; ij++) {
        int di = ij / 3 - 1, dj = ij % 3 - 1;
        int y = py + di, x = px + dj;
        if ((unsigned)y < 16u && (unsigned)x < 16u) {
            int u = y * 16 + x;
            ss += g_R[u * 256 + u];
        }
    }
    float norm = fmaxf(sqrtf(ss), 1e-4f);
    #pragma unroll
    for (int ij = 0; ij < 9; ij++) {
        int di = ij / 3 - 1, dj = ij % 3 - 1;
        int y = qy + di, x = qx + dj;
        sr[ij][tid] = ((unsigned)y < 16u && (unsigned)x < 16u)
                    ? g_R[(y * 16 + x) * 256 + tid] : 0.f;
    }
    __syncthreads();
    float v = 0.f;
    #pragma unroll
    for (int ij = 0; ij < 9; ij++) {
        int di = ij / 3 - 1, dj = ij % 3 - 1;
        int y = py + di, x = px + dj;
        if ((unsigned)y < 16u && (unsigned)x < 16u) v += sr[ij][y * 16 + x];
    }
    v = v * 10.f / norm;
    red[p] = v; __syncthreads();
    for (int s = 128; s > 0; s >>= 1) { if (p < s) red[p] = fmaxf(red[p], red[p + s]); __syncthreads(); }
    float mx = red[0]; __syncthreads();
    float e = __expf(v - mx);
    red[p] = e; __syncthreads();
    for (int s = 128; s > 0; s >>= 1) { if (p < s) red[p] += red[p + s]; __syncthreads(); }
    float inv = 1.f / red[0];
    g_attnT[q * 256 + p] = e * inv;
}

// ---------------- 9) scatter deconv taps -> out_32 pixel-major ----------------
__global__ __launch_bounds__(512) void ral_out_kernel() {
    int pix = blockIdx.x;
    int ho = pix >> 5, wo = pix & 31;
    int c = threadIdx.x;
    float acc = 0.f;
    for (int ki = (ho + 1) & 1; ki < 4; ki += 2) {
        int qy = (ho + 1 - ki) >> 1;
        if ((unsigned)qy >= 16u) continue;
        for (int kj = (wo + 1) & 1; kj < 4; kj += 2) {
            int qx = (wo + 1 - kj) >> 1;
            if ((unsigned)qx >= 16u) continue;
            int q = qy * 16 + qx;
            acc += g_T[(size_t)q * 8192 + (ki * 4 + kj) * 512 + c];
        }
    }
    g_out32T[(size_t)pix * 512 + c] = acc * 0.25f;
}

// ------ 10a) separable gaussian stage 1 ------
__global__ __launch_bounds__(128) void gauss1_kernel() {
    int y = blockIdx.x;
    int cc = blockIdx.y;
    int c = cc * 128 + threadIdx.x;
    __shared__ float gxs[32 * 32];
    for (int e = threadIdx.x; e < 1024; e += 128) {
        int i = e >> 5, xx = e & 31;
        float d = (float)(xx - i);
        gxs[e] = __expf(-d * d * (1.f / 4.5f));
    }
    __syncthreads();
    float vals[32];
    #pragma unroll
    for (int xx = 0; xx < 32; xx++)
        vals[xx] = g_out32T[(size_t)(xx * 32 + y) * 512 + c];
    for (int i = 0; i < 32; i++) {
        float acc = 0.f;
        const float* gr = &gxs[i * 32];
        #pragma unroll
        for (int xx = 0; xx < 32; xx++) acc += gr[xx] * vals[xx];
        g_T[(size_t)(i * 32 + y) * 512 + c] = acc;
    }
}

// ------ 10b) stage 2 ------
__global__ __launch_bounds__(128) void gauss2_kernel() {
    int i = blockIdx.x;
    int cc = blockIdx.y;
    int c = cc * 128 + threadIdx.x;
    const float scale = 1.f / (2.f * 3.14159265358979323846f * 2.25f);
    __shared__ float gys[32 * 32];
    for (int e = threadIdx.x; e < 1024; e += 128) {
        int k = e >> 5, yy = e & 31;
        float d = (float)(yy - k);
        gys[e] = __expf(-d * d * (1.f / 4.5f));
    }
    __syncthreads();
    float vals[32];
    #pragma unroll
    for (int yy = 0; yy < 32; yy++)
        vals[yy] = g_T[(size_t)(i * 32 + yy) * 512 + c];
    for (int k = 0; k < 32; k++) {
        float acc = 0.f;
        const float* gr = &gys[k * 32];
        #pragma unroll
        for (int yy = 0; yy < 32; yy++) acc += gr[yy] * vals[yy];
        g_z[(size_t)(i * 32 + k) * 512 + c] = acc * scale;
    }
}

// ---------------- 11) CSA (inline sigmoids) ----------------
__global__ __launch_bounds__(512) void csa_kernel() {
    int pos = blockIdx.x;
    int y = pos >> 5, x = pos & 31;
    int c = threadIdx.x;
    __shared__ float s_sum[16 * 9];
    __shared__ float s_a[9];
    float center = g_out32T[(size_t)pos * 512 + c];
    float sc = 1.f / (1.f + __expf(-center));
    float nb[9], pr[9];
    #pragma unroll
    for (int ij = 0; ij < 9; ij++) {
        int di = ij / 3 - 1, dj = ij % 3 - 1;
        int yy = y + di, xx = x + dj;
        bool ok = (unsigned)yy < 32u && (unsigned)xx < 32u;
        float v = ok ? g_out32T[(size_t)(yy * 32 + xx) * 512 + c] : 0.f;
        nb[ij] = v;
        float sn = ok ? 1.f / (1.f + __expf(-v)) : 0.f;
        pr[ij] = sc * sn;
    }
    #pragma unroll
    for (int ij = 0; ij < 9; ij++)
        #pragma unroll
        for (int o = 16; o > 0; o >>= 1) pr[ij] += __shfl_down_sync(0xFFFFFFFFu, pr[ij], o);
    int w = c >> 5, l = c & 31;
    if (l == 0) {
        #pragma unroll
        for (int ij = 0; ij < 9; ij++) s_sum[w * 9 + ij] = pr[ij];
    }
    __syncthreads();
    if (c < 9) {
        float t = 0.f;
        for (int w2 = 0; w2 < 16; w2++) t += s_sum[w2 * 9 + c];
        s_a[c] = t * (1.f / 512.f);
    }
    __syncthreads();
    if (c == 0) {
        float mx = s_a[0];
        for (int ij = 1; ij < 9; ij++) mx = fmaxf(mx, s_a[ij]);
        float sum = 0.f; float e[9];
        for (int ij = 0; ij < 9; ij++) { e[ij] = __expf(s_a[ij] - mx); sum += e[ij]; }
        float invs = 1.f / sum;
        for (int ij = 0; ij < 9; ij++) s_a[ij] = e[ij] * invs;
    }
    __syncthreads();
    float out = 0.f;
    #pragma unroll
    for (int ij = 0; ij < 9; ij++) out += s_a[ij] * nb[ij];
    g_z[512 * 1024 + (size_t)pos * 512 + c] = out;
}

// ------------- instance norm + leaky relu; sums npart slices; optional concat copy ----
__global__ __launch_bounds__(256) void norm_leaky_kernel(
    const float* __restrict__ in, int npart, float* __restrict__ outA,
    const float* __restrict__ cpsrc, float* __restrict__ outB) {
    __shared__ float s_red[64];
    int c = blockIdx.x, tid = threadIdx.x;
    float v[4]; float s = 0.f, s2 = 0.f;
    #pragma unroll
    for (int q = 0; q < 4; q++) {
        int idx = c * 1024 + tid + q * 256;
        float acc = in[idx];
        for (int z = 1; z < npart; z++) acc += in[(size_t)z * 512 * 1024 + idx];
        v[q] = acc;
        s += acc; s2 += acc * acc;
    }
    blockReduce2(s, s2, s_red);
    float mu = s * (1.f / 1024.f);
    float inv = rsqrtf(s2 * (1.f / 1024.f) - mu * mu + 1e-5f);
    #pragma unroll
    for (int q = 0; q < 4; q++) {
        float f = (v[q] - mu) * inv;
        outA[c * 1024 + tid + q * 256] = f >= 0.f ? f : 0.2f * f;
    }
    if (cpsrc != nullptr) {
        #pragma unroll
        for (int q = 0; q < 4; q++)
            outB[c * 1024 + tid + q * 256] = cpsrc[c * 1024 + tid + q * 256];
    }
}

// ---------------- host ----------------
extern "C" void kernel_launch(void* const* d_in, const int* in_sizes, int n_in,
                              void* d_out, int out_size) {
    const float* x     = (const float*)d_in[0];
    const float* w_sk3 = (const float*)d_in[2];
    const float* b_sk3 = (const float*)d_in[3];
    const float* w_sk5 = (const float*)d_in[4];
    const float* b_sk5 = (const float*)d_in[5];
    const float* w_sk7 = (const float*)d_in[6];
    const float* b_sk7 = (const float*)d_in[7];
    const float* w_fc  = (const float*)d_in[8];
    const float* b_fc  = (const float*)d_in[9];
    const float* w_fc0 = (const float*)d_in[10];
    const float* b_fc0 = (const float*)d_in[11];
    const float* w_fc1 = (const float*)d_in[12];
    const float* b_fc1 = (const float*)d_in[13];
    const float* w_fc2 = (const float*)d_in[14];
    const float* b_fc2 = (const float*)d_in[15];
    const float* w_down = (const float*)d_in[16];
    const float* w_fuse = (const float*)d_in[17];

    float *fgsT, *S, *R, *attnT, *T, *z, *d1, *z2, *outres;
    cudaGetSymbolAddress((void**)&fgsT, g_fgsT);
    cudaGetSymbolAddress((void**)&S, g_S);
    cudaGetSymbolAddress((void**)&R, g_R);
    cudaGetSymbolAddress((void**)&attnT, g_attnT);
    cudaGetSymbolAddress((void**)&T, g_T);
    cudaGetSymbolAddress((void**)&z, g_z);
    cudaGetSymbolAddress((void**)&d1, g_d1);
    cudaGetSymbolAddress((void**)&z2, g_z2);
    cudaGetSymbolAddress((void**)&outres, g_outres);

    // SKConv all branches (2 oc per block)
    sk_conv_all<<<dim3(256, 3), 128>>>(x, w_sk3, b_sk3, w_sk5, b_sk5, w_sk7, b_sk7);
    fz_kernel<<<32, 256>>>(w_fc, b_fc);
    combine_kernel<<<512, 256>>>(w_fc0, b_fc0, w_fc1, b_fc1, w_fc2, b_fc2);
    // RAL Gram matrix R = F F^T (fp32, 64x64 tiles, k-tile 16, split-K 8)
    gemm64_nt<<<dim3(4, 4, 8), 256>>>(fgsT, S, 256, 512, 8);
    reduceN_kernel<<<256, 256>>>(S, R, 256 * 256, 8);
    score_softmax_kernel<<<256, 256>>>();
    // deconv-as-GEMM (bf16x2): T' = attnT * gather(bg)^T
    gemm128_bf16<true, true><<<dim3(64, 2, 1), 256>>>(attnT, outres, T, 256, 8192, 256, 1);
    ral_out_kernel<<<1024, 512>>>();
    // separable gaussian -> first half of z
    gauss1_kernel<<<dim3(32, 4), 128>>>();
    gauss2_kernel<<<dim3(32, 4), 128>>>();
    // CSA -> second half of z
    csa_kernel<<<1024, 512>>>();
    // down 1x1 conv (bf16x2, split-K 4) + IN + leaky, concat out_res
    gemm128_bf16<false, false><<<dim3(8, 4, 4), 256>>>(w_down, z, d1, 512, 1024, 1024, 4);
    norm_leaky_kernel<<<512, 256>>>(d1, 4, z2, outres, z2 + 512 * 1024);
    // fuse 1x1 conv (bf16x2, split-K 4) + IN + leaky -> output
    gemm128_bf16<false, false><<<dim3(8, 4, 4), 256>>>(w_fuse, z2, d1, 512, 1024, 1024, 4);
    norm_leaky_kernel<<<512, 256>>>(d1, 4, (float*)d_out, nullptr, nullptr);
}